// round 3
// baseline (speedup 1.0000x reference)
#include <cuda_runtime.h>
#include <mma.h>

using namespace nvcuda;

#define BB   2
#define SS   2048
#define DD   1024
#define HH   16
#define DH   64

// Scratch (allocation-free rule: __device__ globals)
__device__ float g_q[BB * HH * SS * DH];
__device__ float g_k[BB * HH * SS * DH];
__device__ float g_v[BB * HH * SS * DH];
__device__ float g_ctx[BB * SS * DD];

using FragA  = wmma::fragment<wmma::matrix_a, 16, 16, 8, wmma::precision::tf32, wmma::row_major>;
using FragBr = wmma::fragment<wmma::matrix_b, 16, 16, 8, wmma::precision::tf32, wmma::row_major>;
using FragBc = wmma::fragment<wmma::matrix_b, 16, 16, 8, wmma::precision::tf32, wmma::col_major>;
using FragC  = wmma::fragment<wmma::accumulator, 16, 16, 8, float>;

__device__ __forceinline__ float tf32r(float x) { return wmma::__float_to_tf32(x); }

// ---------------------------------------------------------------------------
// Projection GEMM: 128x128 CTA tile, BK=32, 256 threads (8 warps, 4M x 2N),
// register-staged double buffering. out = A[4096,1024] @ W[1024,1024] + bias.
// head_layout=1 -> scatter to [B,H,S,DH].
// ---------------------------------------------------------------------------
#define PBM 128
#define PBN 128
#define PBK 32
#define PLDA 36
#define PLDB 132
#define PLDC 132

#define PROJ_SMEM_FLOATS (2 * PBM * PLDA + 2 * PBK * PLDB)   // 17664
#define PROJ_SMEM_BYTES  (PROJ_SMEM_FLOATS * 4)              // 70656

__device__ __forceinline__ void gemm128(const float* __restrict__ A,
                                        const float* __restrict__ W,
                                        const float* __restrict__ bias,
                                        float* __restrict__ out,
                                        int head_layout)
{
    extern __shared__ float sm[];
    float* As = sm;                       // [2][128*36]
    float* Bs = sm + 2 * PBM * PLDA;      // [2][32*132]
    float* Cs = sm;                       // reuse for epilogue (16896 floats)

    const int tid  = threadIdx.x;
    const int warp = tid >> 5;
    const int wm   = warp >> 1;           // 0..3
    const int wn   = warp & 1;            // 0..1
    const int n0   = blockIdx.x * PBN;
    const int m0   = blockIdx.y * PBM;

    FragC acc[2][4];
#pragma unroll
    for (int mf = 0; mf < 2; mf++)
#pragma unroll
        for (int nf = 0; nf < 4; nf++) wmma::fill_fragment(acc[mf][nf], 0.0f);

    float4 aR[4], bR[4];

    auto loadTiles = [&](int kt) {
#pragma unroll
        for (int t = 0; t < 4; t++) {
            int chunk = tid + t * 256;
            int r = chunk >> 3, c = (chunk & 7) * 4;
            aR[t] = *reinterpret_cast<const float4*>(A + (size_t)(m0 + r) * DD + kt + c);
        }
#pragma unroll
        for (int t = 0; t < 4; t++) {
            int chunk = tid + t * 256;
            int r = chunk >> 5, c = (chunk & 31) * 4;
            bR[t] = *reinterpret_cast<const float4*>(W + (size_t)(kt + r) * DD + n0 + c);
        }
    };
    auto storeTiles = [&](int buf) {
        float* Ab = As + buf * PBM * PLDA;
        float* Bb = Bs + buf * PBK * PLDB;
#pragma unroll
        for (int t = 0; t < 4; t++) {
            int chunk = tid + t * 256;
            int r = chunk >> 3, c = (chunk & 7) * 4;
            float4 v = aR[t];
            v.x = tf32r(v.x); v.y = tf32r(v.y); v.z = tf32r(v.z); v.w = tf32r(v.w);
            *reinterpret_cast<float4*>(Ab + r * PLDA + c) = v;
        }
#pragma unroll
        for (int t = 0; t < 4; t++) {
            int chunk = tid + t * 256;
            int r = chunk >> 5, c = (chunk & 31) * 4;
            float4 v = bR[t];
            v.x = tf32r(v.x); v.y = tf32r(v.y); v.z = tf32r(v.z); v.w = tf32r(v.w);
            *reinterpret_cast<float4*>(Bb + r * PLDB + c) = v;
        }
    };

    loadTiles(0);
    storeTiles(0);
    __syncthreads();

    const int NT = DD / PBK;   // 32
    for (int it = 0; it < NT; it++) {
        const int buf = it & 1;
        if (it + 1 < NT) loadTiles((it + 1) * PBK);   // overlap with compute

        const float* Ab = As + buf * PBM * PLDA;
        const float* Bb = Bs + buf * PBK * PLDB;
        FragA a[2]; FragBr b[4];
#pragma unroll
        for (int kk = 0; kk < PBK; kk += 8) {
#pragma unroll
            for (int mf = 0; mf < 2; mf++)
                wmma::load_matrix_sync(a[mf], Ab + (wm * 32 + mf * 16) * PLDA + kk, PLDA);
#pragma unroll
            for (int nf = 0; nf < 4; nf++)
                wmma::load_matrix_sync(b[nf], Bb + kk * PLDB + wn * 64 + nf * 16, PLDB);
#pragma unroll
            for (int mf = 0; mf < 2; mf++)
#pragma unroll
                for (int nf = 0; nf < 4; nf++)
                    wmma::mma_sync(acc[mf][nf], a[mf], b[nf], acc[mf][nf]);
        }
        __syncthreads();
        if (it + 1 < NT) storeTiles(buf ^ 1);
        __syncthreads();
    }

    // Epilogue: stage to smem, add bias, store coalesced
#pragma unroll
    for (int mf = 0; mf < 2; mf++)
#pragma unroll
        for (int nf = 0; nf < 4; nf++)
            wmma::store_matrix_sync(Cs + (wm * 32 + mf * 16) * PLDC + wn * 64 + nf * 16,
                                    acc[mf][nf], PLDC, wmma::mem_row_major);
    __syncthreads();

#pragma unroll
    for (int t = 0; t < 16; t++) {
        int chunk = tid + t * 256;
        int r = chunk >> 5, c = (chunk & 31) * 4;
        float4 v = *reinterpret_cast<const float4*>(Cs + r * PLDC + c);
        float4 bi = *reinterpret_cast<const float4*>(bias + n0 + c);
        v.x += bi.x; v.y += bi.y; v.z += bi.z; v.w += bi.w;
        int m = m0 + r;
        if (head_layout) {
            int h = (n0 + c) >> 6, d = (n0 + c) & 63;
            int bb = m >> 11, s = m & 2047;
            *reinterpret_cast<float4*>(out + (size_t)((bb * HH + h) * SS + s) * DH + d) = v;
        } else {
            *reinterpret_cast<float4*>(out + (size_t)m * DD + n0 + c) = v;
        }
    }
}

__global__ void __launch_bounds__(256) proj_qkv_kernel(
    const float* __restrict__ q, const float* __restrict__ k, const float* __restrict__ v,
    const float* __restrict__ Wq, const float* __restrict__ Wk, const float* __restrict__ Wv,
    const float* __restrict__ bq, const float* __restrict__ bk, const float* __restrict__ bv)
{
    const int z = blockIdx.z;
    const float* A    = (z == 0) ? q  : (z == 1) ? k  : v;
    const float* W    = (z == 0) ? Wq : (z == 1) ? Wk : Wv;
    const float* bias = (z == 0) ? bq : (z == 1) ? bk : bv;
    float*       out  = (z == 0) ? g_q : (z == 1) ? g_k : g_v;
    gemm128(A, W, bias, out, 1);
}

__global__ void __launch_bounds__(256) proj_out_kernel(
    const float* __restrict__ Wo, const float* __restrict__ bo, float* __restrict__ out)
{
    gemm128(g_ctx, Wo, bo, out, 0);
}

// ---------------------------------------------------------------------------
// Flash attention: BM=128 q rows per CTA, BN=64 keys/iter, 256 threads
// (8 warps, 4M x 2N, warp tile 32x32). Softmax: 2 threads per row.
// ---------------------------------------------------------------------------
#define ALD 68
#define ATTN_SMEM_FLOATS (ALD * (128 + 64 + 64 + 128 + 128) + 128 + 128 + 64)  // 35136
#define ATTN_SMEM_BYTES  (ATTN_SMEM_FLOATS * 4)                                // 140544

__global__ void __launch_bounds__(256) attn_kernel(const float* __restrict__ mask)
{
    extern __shared__ float sm[];
    float* Qs    = sm;                    // 128 x ALD
    float* Ks    = Qs + 128 * ALD;        // 64 x ALD
    float* Vs    = Ks + 64 * ALD;         // 64 x ALD
    float* Ss    = Vs + 64 * ALD;         // 128 x ALD
    float* Os    = Ss + 128 * ALD;        // 128 x ALD
    float* m_i   = Os + 128 * ALD;        // 128
    float* l_i   = m_i + 128;             // 128
    float* maskS = l_i + 128;             // 64

    const int tid  = threadIdx.x;
    const int warp = tid >> 5;
    const int wm   = warp >> 1;           // 0..3 (32-row strip)
    const int wn   = warp & 1;            // 0..1 (32-col strip)
    const int bh   = blockIdx.x;          // b*16 + h
    const int qt   = blockIdx.y;          // 0..15
    const int bb   = bh >> 4;
    const int h    = bh & 15;

    const float* Qg = g_q + (size_t)(bh * SS + qt * 128) * DH;
    const float* Kg = g_k + (size_t)bh * SS * DH;
    const float* Vg = g_v + (size_t)bh * SS * DH;

    // Load Q tile (tf32) and zero O accumulator
#pragma unroll
    for (int t = 0; t < 8; t++) {
        int chunk = tid + t * 256;
        int r = chunk >> 4, c = (chunk & 15) * 4;
        float4 v = *reinterpret_cast<const float4*>(Qg + r * DH + c);
        v.x = tf32r(v.x); v.y = tf32r(v.y); v.z = tf32r(v.z); v.w = tf32r(v.w);
        *reinterpret_cast<float4*>(Qs + r * ALD + c) = v;
        *reinterpret_cast<float4*>(Os + r * ALD + c) = make_float4(0.f, 0.f, 0.f, 0.f);
    }
    if (tid < 128) { m_i[tid] = -1e30f; l_i[tid] = 0.f; }
    __syncthreads();

    for (int kt0 = 0; kt0 < SS; kt0 += 64) {
        // Load K/V tiles + mask strip
#pragma unroll
        for (int t = 0; t < 4; t++) {
            int chunk = tid + t * 256;
            int r = chunk >> 4, c = (chunk & 15) * 4;
            float4 kv = *reinterpret_cast<const float4*>(Kg + (kt0 + r) * DH + c);
            kv.x = tf32r(kv.x); kv.y = tf32r(kv.y); kv.z = tf32r(kv.z); kv.w = tf32r(kv.w);
            *reinterpret_cast<float4*>(Ks + r * ALD + c) = kv;
            float4 vv = *reinterpret_cast<const float4*>(Vg + (kt0 + r) * DH + c);
            vv.x = tf32r(vv.x); vv.y = tf32r(vv.y); vv.z = tf32r(vv.z); vv.w = tf32r(vv.w);
            *reinterpret_cast<float4*>(Vs + r * ALD + c) = vv;
        }
        if (tid < 64) maskS[tid] = mask[bb * SS + kt0 + tid] * (-1e9f);
        __syncthreads();

        // S = Q @ K^T  (128x64, k = DH = 64), warp tile 32x32
        {
            FragC s[2][2];
#pragma unroll
            for (int mf = 0; mf < 2; mf++)
#pragma unroll
                for (int nf = 0; nf < 2; nf++) wmma::fill_fragment(s[mf][nf], 0.0f);
            FragA a[2]; FragBc b[2];
#pragma unroll
            for (int kk = 0; kk < DH; kk += 8) {
#pragma unroll
                for (int mf = 0; mf < 2; mf++)
                    wmma::load_matrix_sync(a[mf], Qs + (wm * 32 + mf * 16) * ALD + kk, ALD);
#pragma unroll
                for (int nf = 0; nf < 2; nf++)
                    wmma::load_matrix_sync(b[nf], Ks + (wn * 32 + nf * 16) * ALD + kk, ALD);
#pragma unroll
                for (int mf = 0; mf < 2; mf++)
#pragma unroll
                    for (int nf = 0; nf < 2; nf++)
                        wmma::mma_sync(s[mf][nf], a[mf], b[nf], s[mf][nf]);
            }
#pragma unroll
            for (int mf = 0; mf < 2; mf++)
#pragma unroll
                for (int nf = 0; nf < 2; nf++)
                    wmma::store_matrix_sync(Ss + (wm * 32 + mf * 16) * ALD + wn * 32 + nf * 16,
                                            s[mf][nf], ALD, wmma::mem_row_major);
        }
        __syncthreads();

        // Online softmax: 2 threads per row (32-col strips), shfl combine
        {
            const int r  = tid >> 1;
            const int hh = tid & 1;
            const int cb = hh * 32;
            float* row = Ss + r * ALD + cb;
            const float mo = m_i[r];
            float mx = -1e30f;
#pragma unroll
            for (int c = 0; c < 32; c++) {
                float s = row[c] * 0.125f + maskS[cb + c];
                row[c] = s;
                mx = fmaxf(mx, s);
            }
            mx = fmaxf(mx, __shfl_xor_sync(0xffffffffu, mx, 1));
            mx = fmaxf(mx, mo);
            const float alpha = __expf(mo - mx);
            float sum = 0.f;
#pragma unroll
            for (int c = 0; c < 32; c++) {
                float p = __expf(row[c] - mx);
                sum += p;
                row[c] = tf32r(p);
            }
            sum += __shfl_xor_sync(0xffffffffu, sum, 1);
            if (hh == 0) { m_i[r] = mx; l_i[r] = l_i[r] * alpha + sum; }
            float* orow = Os + r * ALD + cb;
#pragma unroll
            for (int c = 0; c < 32; c++) orow[c] *= alpha;
        }
        __syncthreads();

        // O += P @ V  (128x64, k = 64), warp tile 32x32
        {
            FragC o[2][2];
#pragma unroll
            for (int mf = 0; mf < 2; mf++)
#pragma unroll
                for (int nf = 0; nf < 2; nf++)
                    wmma::load_matrix_sync(o[mf][nf],
                        Os + (wm * 32 + mf * 16) * ALD + wn * 32 + nf * 16, ALD,
                        wmma::mem_row_major);
            FragA a[2]; FragBr b[2];
#pragma unroll
            for (int kk = 0; kk < 64; kk += 8) {
#pragma unroll
                for (int mf = 0; mf < 2; mf++)
                    wmma::load_matrix_sync(a[mf], Ss + (wm * 32 + mf * 16) * ALD + kk, ALD);
#pragma unroll
                for (int nf = 0; nf < 2; nf++)
                    wmma::load_matrix_sync(b[nf], Vs + kk * ALD + wn * 32 + nf * 16, ALD);
#pragma unroll
                for (int mf = 0; mf < 2; mf++)
#pragma unroll
                    for (int nf = 0; nf < 2; nf++)
                        wmma::mma_sync(o[mf][nf], a[mf], b[nf], o[mf][nf]);
            }
#pragma unroll
            for (int mf = 0; mf < 2; mf++)
#pragma unroll
                for (int nf = 0; nf < 2; nf++)
                    wmma::store_matrix_sync(Os + (wm * 32 + mf * 16) * ALD + wn * 32 + nf * 16,
                                            o[mf][nf], ALD, wmma::mem_row_major);
        }
        __syncthreads();
    }

    // Epilogue: normalize, scatter to [B,S,D] ctx
#pragma unroll
    for (int t = 0; t < 8; t++) {
        int chunk = tid + t * 256;
        int r = chunk >> 4, c = (chunk & 15) * 4;
        float inv = 1.0f / l_i[r];
        float4 v = *reinterpret_cast<const float4*>(Os + r * ALD + c);
        v.x *= inv; v.y *= inv; v.z *= inv; v.w *= inv;
        *reinterpret_cast<float4*>(
            g_ctx + (size_t)(bb * SS + qt * 128 + r) * DD + h * DH + c) = v;
    }
}

// ---------------------------------------------------------------------------
extern "C" void kernel_launch(void* const* d_in, const int* in_sizes, int n_in,
                              void* d_out, int out_size)
{
    const float* query = (const float*)d_in[0];
    const float* key   = (const float*)d_in[1];
    const float* value = (const float*)d_in[2];
    const float* mask  = (const float*)d_in[3];
    const float* Wq    = (const float*)d_in[4];
    const float* bq    = (const float*)d_in[5];
    const float* Wk    = (const float*)d_in[6];
    const float* bk    = (const float*)d_in[7];
    const float* Wv    = (const float*)d_in[8];
    const float* bv    = (const float*)d_in[9];
    const float* Wo    = (const float*)d_in[10];
    const float* bo    = (const float*)d_in[11];
    float* out = (float*)d_out;

    static int configured = 0;
    if (!configured) {
        cudaFuncSetAttribute(proj_qkv_kernel, cudaFuncAttributeMaxDynamicSharedMemorySize, PROJ_SMEM_BYTES);
        cudaFuncSetAttribute(proj_out_kernel, cudaFuncAttributeMaxDynamicSharedMemorySize, PROJ_SMEM_BYTES);
        cudaFuncSetAttribute(attn_kernel,     cudaFuncAttributeMaxDynamicSharedMemorySize, ATTN_SMEM_BYTES);
        configured = 1;
    }

    // 1) Q/K/V projections into split-head scratch
    proj_qkv_kernel<<<dim3(8, 32, 3), 256, PROJ_SMEM_BYTES>>>(query, key, value, Wq, Wk, Wv, bq, bk, bv);
    // 2) Flash attention -> g_ctx [B,S,D]
    attn_kernel<<<dim3(32, 16), 256, ATTN_SMEM_BYTES>>>(mask);
    // 3) Output projection -> d_out
    proj_out_kernel<<<dim3(8, 32), 256, PROJ_SMEM_BYTES>>>(Wo, bo, out);
}

// round 5
// speedup vs baseline: 3.9276x; 3.9276x over previous
#include <cuda_runtime.h>
#include <cuda_fp16.h>
#include <mma.h>
#include <cstdint>

using namespace nvcuda;

#define BB 2
#define SS 2048
#define DD 1024
#define HH 16
#define DH 64

// ---- scratch (__device__ globals; no allocations allowed) ----
__device__ __half c_q[BB * SS * DD], c_k[BB * SS * DD], c_v[BB * SS * DD];
__device__ __half c_wq[DD * DD], c_wk[DD * DD], c_wv[DD * DD], c_wo[DD * DD];
__device__ __half hq[BB * HH * SS * DH], hk[BB * HH * SS * DH], hv[BB * HH * SS * DH];
__device__ __half hctx[BB * SS * DD];

// ---------------- helpers ----------------
__device__ __forceinline__ uint32_t smem_u32(const void* p) {
    uint32_t a;
    asm("{ .reg .u64 t; cvta.to.shared.u64 t, %1; cvt.u32.u64 %0, t; }" : "=r"(a) : "l"(p));
    return a;
}
__device__ __forceinline__ void cp16(uint32_t d, const void* s) {
    asm volatile("cp.async.ca.shared.global [%0], [%1], 16;" :: "r"(d), "l"(s) : "memory");
}
__device__ __forceinline__ uint32_t h2u(__half2 h) { return *reinterpret_cast<uint32_t*>(&h); }

__device__ __forceinline__ void mma16(float* d, uint32_t a0, uint32_t a1, uint32_t a2, uint32_t a3,
                                      uint32_t b0, uint32_t b1) {
    asm volatile(
        "mma.sync.aligned.m16n8k16.row.col.f32.f16.f16.f32 "
        "{%0,%1,%2,%3},{%4,%5,%6,%7},{%8,%9},{%0,%1,%2,%3};"
        : "+f"(d[0]), "+f"(d[1]), "+f"(d[2]), "+f"(d[3])
        : "r"(a0), "r"(a1), "r"(a2), "r"(a3), "r"(b0), "r"(b1));
}

// ---------------------------------------------------------------------------
// fp32 -> fp16 conversion (activations + weights), one launch, 7 jobs
// ---------------------------------------------------------------------------
__global__ void __launch_bounds__(256) convert_kernel(
    const float* __restrict__ q, const float* __restrict__ k, const float* __restrict__ v,
    const float* __restrict__ Wq, const float* __restrict__ Wk,
    const float* __restrict__ Wv, const float* __restrict__ Wo)
{
    const float* src; __half* dst; int n;
    switch (blockIdx.y) {
        case 0: src = q;  dst = c_q;  n = BB * SS * DD; break;
        case 1: src = k;  dst = c_k;  n = BB * SS * DD; break;
        case 2: src = v;  dst = c_v;  n = BB * SS * DD; break;
        case 3: src = Wq; dst = c_wq; n = DD * DD; break;
        case 4: src = Wk; dst = c_wk; n = DD * DD; break;
        case 5: src = Wv; dst = c_wv; n = DD * DD; break;
        default: src = Wo; dst = c_wo; n = DD * DD; break;
    }
    const int n4 = n >> 2;
    for (int i = blockIdx.x * 256 + threadIdx.x; i < n4; i += gridDim.x * 256) {
        float4 f = reinterpret_cast<const float4*>(src)[i];
        reinterpret_cast<__half2*>(dst)[2 * i]     = __floats2half2_rn(f.x, f.y);
        reinterpret_cast<__half2*>(dst)[2 * i + 1] = __floats2half2_rn(f.z, f.w);
    }
}

// ---------------------------------------------------------------------------
// fp16 GEMM: out = A[4096,1024] @ W[1024,1024] + bias
// 128x128 CTA tile, BK=32, 256 threads (8 warps 4Mx2N), cp.async double buffer.
// half_head=1 -> half output scattered to [B,H,S,DH]; else fp32 [M,N].
// ---------------------------------------------------------------------------
#define PALD 40     // A row pitch (halves)
#define PBLD 136    // B row pitch (halves)
#define PROJ_SMEM_BYTES 37888   // A: 2*10240  B: 2*8704 ; epilogue aliases (36864)

using AF = wmma::fragment<wmma::matrix_a, 16, 16, 16, __half, wmma::row_major>;
using BF = wmma::fragment<wmma::matrix_b, 16, 16, 16, __half, wmma::row_major>;
using CF = wmma::fragment<wmma::accumulator, 16, 16, 16, float>;

__device__ __forceinline__ void gemm_fp16(const __half* __restrict__ A,
                                          const __half* __restrict__ Wm,
                                          const float* __restrict__ bias,
                                          void* __restrict__ outp, int half_head)
{
    extern __shared__ char dsm[];
    const uint32_t sb = smem_u32(dsm);
    const int tid  = threadIdx.x;
    const int warp = tid >> 5;
    const int lid  = tid & 31;
    const int wm   = warp >> 1;
    const int wn   = warp & 1;
    const int n0   = blockIdx.x * 128;
    const int m0   = blockIdx.y * 128;

    CF acc[2][4];
#pragma unroll
    for (int mf = 0; mf < 2; mf++)
#pragma unroll
        for (int nf = 0; nf < 4; nf++) wmma::fill_fragment(acc[mf][nf], 0.0f);

    auto issue = [&](int it) {
        const int kt = it * 32, buf = it & 1;
        const uint32_t ad = sb + buf * 10240;
        const uint32_t bd = sb + 20480 + buf * 8704;
#pragma unroll
        for (int t = 0; t < 2; t++) {
            int id = tid + t * 256;                       // A: 128 rows x 4 x 16B
            cp16(ad + (id >> 2) * 80 + (id & 3) * 16,
                 A + (size_t)(m0 + (id >> 2)) * DD + kt + (id & 3) * 8);
        }
#pragma unroll
        for (int t = 0; t < 2; t++) {
            int id = tid + t * 256;                       // B: 32 rows x 16 x 16B
            cp16(bd + (id >> 4) * 272 + (id & 15) * 16,
                 Wm + (size_t)(kt + (id >> 4)) * DD + n0 + (id & 15) * 8);
        }
        asm volatile("cp.async.commit_group;" ::: "memory");
    };

    issue(0);
    issue(1);
    for (int it = 0; it < 32; it++) {
        if (it < 31) asm volatile("cp.async.wait_group 1;" ::: "memory");
        else         asm volatile("cp.async.wait_group 0;" ::: "memory");
        __syncthreads();
        const __half* Ab = reinterpret_cast<const __half*>(dsm) + (it & 1) * 5120;
        const __half* Bb = reinterpret_cast<const __half*>(dsm + 20480) + (it & 1) * 4352;
        AF a[2]; BF b[4];
#pragma unroll
        for (int kk = 0; kk < 32; kk += 16) {
#pragma unroll
            for (int mf = 0; mf < 2; mf++)
                wmma::load_matrix_sync(a[mf], Ab + (wm * 32 + mf * 16) * PALD + kk, PALD);
#pragma unroll
            for (int nf = 0; nf < 4; nf++)
                wmma::load_matrix_sync(b[nf], Bb + kk * PBLD + wn * 64 + nf * 16, PBLD);
#pragma unroll
            for (int mf = 0; mf < 2; mf++)
#pragma unroll
                for (int nf = 0; nf < 4; nf++)
                    wmma::mma_sync(acc[mf][nf], a[mf], b[nf], acc[mf][nf]);
        }
        __syncthreads();
        if (it + 2 < 32) issue(it + 2);
    }
    __syncthreads();

    // Epilogue: per-warp smem scratch (aliases pipeline buffers), 2 passes of 32 cols
    float* eps = reinterpret_cast<float*>(dsm) + warp * 1152;   // 32 x 36
    const int m = m0 + wm * 32 + lid;
#pragma unroll
    for (int pass = 0; pass < 2; pass++) {
        wmma::store_matrix_sync(eps,               acc[0][2 * pass],     36, wmma::mem_row_major);
        wmma::store_matrix_sync(eps + 16,          acc[0][2 * pass + 1], 36, wmma::mem_row_major);
        wmma::store_matrix_sync(eps + 16 * 36,     acc[1][2 * pass],     36, wmma::mem_row_major);
        wmma::store_matrix_sync(eps + 16 * 36 + 16, acc[1][2 * pass + 1], 36, wmma::mem_row_major);
        __syncwarp();
        const int nc0 = n0 + wn * 64 + pass * 32;
        if (half_head) {
            const int hh = nc0 >> 6, d = nc0 & 63;
            __half* dst = (__half*)outp +
                ((size_t)((m >> 11) * HH + hh) * SS + (m & 2047)) * DH + d;
#pragma unroll
            for (int c = 0; c < 32; c += 2) {
                float x = eps[lid * 36 + c]     + bias[nc0 + c];
                float y = eps[lid * 36 + c + 1] + bias[nc0 + c + 1];
                *reinterpret_cast<__half2*>(dst + c) = __floats2half2_rn(x, y);
            }
        } else {
            float* dst = (float*)outp + (size_t)m * DD + nc0;
#pragma unroll
            for (int c = 0; c < 32; c++) dst[c] = eps[lid * 36 + c] + bias[nc0 + c];
        }
        __syncwarp();
    }
}

__global__ void __launch_bounds__(256) proj_qkv_kernel()
{
    const int z = blockIdx.z;
    const __half* A = (z == 0) ? c_q  : (z == 1) ? c_k  : c_v;
    const __half* W = (z == 0) ? c_wq : (z == 1) ? c_wk : c_wv;
    __half* out     = (z == 0) ? hq   : (z == 1) ? hk   : hv;
    // biases are zeros in this problem's setup BUT must stay general: fetched via cbuf
    gemm_fp16(A, W, nullptr, out, 1);   // placeholder (replaced below)
}

// NOTE: biases must be passed; real kernels below.
__global__ void __launch_bounds__(256) proj_qkv_kernel2(
    const float* __restrict__ bq, const float* __restrict__ bk, const float* __restrict__ bv)
{
    const int z = blockIdx.z;
    const __half* A    = (z == 0) ? c_q  : (z == 1) ? c_k  : c_v;
    const __half* W    = (z == 0) ? c_wq : (z == 1) ? c_wk : c_wv;
    const float* bias  = (z == 0) ? bq   : (z == 1) ? bk   : bv;
    __half* out        = (z == 0) ? hq   : (z == 1) ? hk   : hv;
    gemm_fp16(A, W, bias, out, 1);
}

__global__ void __launch_bounds__(256) proj_out_kernel(
    const float* __restrict__ bo, float* __restrict__ out)
{
    gemm_fp16(hctx, c_wo, bo, out, 0);
}

// ---------------------------------------------------------------------------
// Flash attention, fp16 mma.sync.m16n8k16, fully register-resident.
// CTA: 128 q rows (8 warps x 16), 64 keys/iter.
// ---------------------------------------------------------------------------
#define KLD 72
#define VLD 72

__global__ void __launch_bounds__(256, 2) attn_kernel(const float* __restrict__ mask)
{
    __shared__ __half Ks[64 * KLD];
    __shared__ __half Vt[64 * VLD];
    __shared__ float maskS[64];

    const int tid  = threadIdx.x;
    const int warp = tid >> 5;
    const int lane = tid & 31;
    const int g    = lane >> 2;
    const int t4   = lane & 3;
    const int wr0  = warp * 16;
    const int bh   = blockIdx.x;
    const int qt   = blockIdx.y;
    const int bb   = bh >> 4;
    const int hi   = bh & 15;

    const __half* Qg = hq + ((size_t)bh * SS + qt * 128 + wr0) * DH;
    const __half* Kg = hk + (size_t)bh * SS * DH;
    const __half* Vg = hv + (size_t)bh * SS * DH;

    // Q fragments straight from global (reused across all 32 key tiles)
    uint32_t Qa[4][4];
#pragma unroll
    for (int kc = 0; kc < 4; kc++) {
        Qa[kc][0] = *reinterpret_cast<const uint32_t*>(Qg + (size_t)g * DH + kc * 16 + 2 * t4);
        Qa[kc][1] = *reinterpret_cast<const uint32_t*>(Qg + (size_t)(g + 8) * DH + kc * 16 + 2 * t4);
        Qa[kc][2] = *reinterpret_cast<const uint32_t*>(Qg + (size_t)g * DH + kc * 16 + 2 * t4 + 8);
        Qa[kc][3] = *reinterpret_cast<const uint32_t*>(Qg + (size_t)(g + 8) * DH + kc * 16 + 2 * t4 + 8);
    }

    float O[8][4];
#pragma unroll
    for (int d = 0; d < 8; d++) { O[d][0] = O[d][1] = O[d][2] = O[d][3] = 0.f; }
    float m0 = -1e30f, m1 = -1e30f, l0 = 0.f, l1 = 0.f;

    for (int kt0 = 0; kt0 < SS; kt0 += 64) {
        __syncthreads();   // previous tile fully consumed
#pragma unroll
        for (int t = 0; t < 2; t++) {
            int idx = tid + t * 256;
            int r = idx >> 3, c = (idx & 7) * 8;
            *reinterpret_cast<uint4*>(Ks + r * KLD + c) =
                *reinterpret_cast<const uint4*>(Kg + (size_t)(kt0 + r) * DH + c);
            union { uint4 u; __half h[8]; } vv;
            vv.u = *reinterpret_cast<const uint4*>(Vg + (size_t)(kt0 + r) * DH + c);
#pragma unroll
            for (int j = 0; j < 8; j++) Vt[(c + j) * VLD + r] = vv.h[j];
        }
        if (tid < 64) maskS[tid] = mask[bb * SS + kt0 + tid] * (-1e9f);
        __syncthreads();

        // S = Q K^T : 8 n-tiles x 4 k-chunks of m16n8k16
        float S[8][4];
#pragma unroll
        for (int j = 0; j < 8; j++) { S[j][0] = S[j][1] = S[j][2] = S[j][3] = 0.f; }
#pragma unroll
        for (int kc = 0; kc < 4; kc++) {
#pragma unroll
            for (int j = 0; j < 8; j++) {
                uint32_t b0 = *reinterpret_cast<const uint32_t*>(Ks + (8 * j + g) * KLD + kc * 16 + 2 * t4);
                uint32_t b1 = *reinterpret_cast<const uint32_t*>(Ks + (8 * j + g) * KLD + kc * 16 + 2 * t4 + 8);
                mma16(S[j], Qa[kc][0], Qa[kc][1], Qa[kc][2], Qa[kc][3], b0, b1);
            }
        }

        // Online softmax on fragments (rows g / g+8; cols 8j+2t4, +1)
        float mx0 = -1e30f, mx1 = -1e30f;
#pragma unroll
        for (int j = 0; j < 8; j++) {
            float k0 = maskS[8 * j + 2 * t4];
            float k1 = maskS[8 * j + 2 * t4 + 1];
            S[j][0] = S[j][0] * 0.125f + k0;
            S[j][1] = S[j][1] * 0.125f + k1;
            S[j][2] = S[j][2] * 0.125f + k0;
            S[j][3] = S[j][3] * 0.125f + k1;
            mx0 = fmaxf(mx0, fmaxf(S[j][0], S[j][1]));
            mx1 = fmaxf(mx1, fmaxf(S[j][2], S[j][3]));
        }
        mx0 = fmaxf(mx0, __shfl_xor_sync(0xffffffffu, mx0, 1));
        mx0 = fmaxf(mx0, __shfl_xor_sync(0xffffffffu, mx0, 2));
        mx1 = fmaxf(mx1, __shfl_xor_sync(0xffffffffu, mx1, 1));
        mx1 = fmaxf(mx1, __shfl_xor_sync(0xffffffffu, mx1, 2));
        const float nm0 = fmaxf(m0, mx0);
        const float nm1 = fmaxf(m1, mx1);
        const float al0 = __expf(m0 - nm0);
        const float al1 = __expf(m1 - nm1);
        m0 = nm0; m1 = nm1;
        float s0 = 0.f, s1 = 0.f;
#pragma unroll
        for (int j = 0; j < 8; j++) {
            S[j][0] = __expf(S[j][0] - nm0);
            S[j][1] = __expf(S[j][1] - nm0);
            S[j][2] = __expf(S[j][2] - nm1);
            S[j][3] = __expf(S[j][3] - nm1);
            s0 += S[j][0] + S[j][1];
            s1 += S[j][2] + S[j][3];
        }
        s0 += __shfl_xor_sync(0xffffffffu, s0, 1);
        s0 += __shfl_xor_sync(0xffffffffu, s0, 2);
        s1 += __shfl_xor_sync(0xffffffffu, s1, 1);
        s1 += __shfl_xor_sync(0xffffffffu, s1, 2);
        l0 = l0 * al0 + s0;
        l1 = l1 * al1 + s1;
#pragma unroll
        for (int d = 0; d < 8; d++) {
            O[d][0] *= al0; O[d][1] *= al0;
            O[d][2] *= al1; O[d][3] *= al1;
        }

        // O += P V : thread-local C->A fragment remap (fp16)
#pragma unroll
        for (int kj = 0; kj < 4; kj++) {
            uint32_t a0 = h2u(__floats2half2_rn(S[2 * kj][0],     S[2 * kj][1]));
            uint32_t a1 = h2u(__floats2half2_rn(S[2 * kj][2],     S[2 * kj][3]));
            uint32_t a2 = h2u(__floats2half2_rn(S[2 * kj + 1][0], S[2 * kj + 1][1]));
            uint32_t a3 = h2u(__floats2half2_rn(S[2 * kj + 1][2], S[2 * kj + 1][3]));
#pragma unroll
            for (int d = 0; d < 8; d++) {
                uint32_t b0 = *reinterpret_cast<const uint32_t*>(Vt + (8 * d + g) * VLD + kj * 16 + 2 * t4);
                uint32_t b1 = *reinterpret_cast<const uint32_t*>(Vt + (8 * d + g) * VLD + kj * 16 + 2 * t4 + 8);
                mma16(O[d], a0, a1, a2, a3, b0, b1);
            }
        }
    }

    // Epilogue: normalize, write half ctx [B,S,D]
    const float inv0 = 1.0f / l0;
    const float inv1 = 1.0f / l1;
    __half* base = hctx + ((size_t)(bb * SS + qt * 128 + wr0)) * DD + hi * DH;
#pragma unroll
    for (int d = 0; d < 8; d++) {
        *reinterpret_cast<__half2*>(base + (size_t)g * DD + 8 * d + 2 * t4) =
            __floats2half2_rn(O[d][0] * inv0, O[d][1] * inv0);
        *reinterpret_cast<__half2*>(base + (size_t)(g + 8) * DD + 8 * d + 2 * t4) =
            __floats2half2_rn(O[d][2] * inv1, O[d][3] * inv1);
    }
}

// ---------------------------------------------------------------------------
extern "C" void kernel_launch(void* const* d_in, const int* in_sizes, int n_in,
                              void* d_out, int out_size)
{
    const float* query = (const float*)d_in[0];
    const float* key   = (const float*)d_in[1];
    const float* value = (const float*)d_in[2];
    const float* mask  = (const float*)d_in[3];
    const float* Wq    = (const float*)d_in[4];
    const float* bq    = (const float*)d_in[5];
    const float* Wk    = (const float*)d_in[6];
    const float* bk    = (const float*)d_in[7];
    const float* Wv    = (const float*)d_in[8];
    const float* bv    = (const float*)d_in[9];
    const float* Wo    = (const float*)d_in[10];
    const float* bo    = (const float*)d_in[11];
    float* out = (float*)d_out;

    convert_kernel<<<dim3(512, 7), 256>>>(query, key, value, Wq, Wk, Wv, Wo);
    proj_qkv_kernel2<<<dim3(8, 32, 3), 256, PROJ_SMEM_BYTES>>>(bq, bk, bv);
    attn_kernel<<<dim3(32, 16), 256>>>(mask);
    proj_out_kernel<<<dim3(8, 32), 256, PROJ_SMEM_BYTES>>>(bo, out);
}

// round 6
// speedup vs baseline: 4.0497x; 1.0311x over previous
#include <cuda_runtime.h>
#include <cuda_fp16.h>
#include <mma.h>
#include <cstdint>

using namespace nvcuda;

#define BB 2
#define SS 2048
#define DD 1024
#define HH 16
#define DH 64

// ---- scratch (__device__ globals; no allocations allowed) ----
__device__ __half c_q[BB * SS * DD], c_k[BB * SS * DD], c_v[BB * SS * DD];
__device__ __half c_wq[DD * DD], c_wk[DD * DD], c_wv[DD * DD], c_wo[DD * DD];
__device__ __half hq[BB * HH * SS * DH], hk[BB * HH * SS * DH], hv[BB * HH * SS * DH];
__device__ __half hctx[BB * SS * DD];

// ---------------- helpers ----------------
__device__ __forceinline__ uint32_t smem_u32(const void* p) {
    uint32_t a;
    asm("{ .reg .u64 t; cvta.to.shared.u64 t, %1; cvt.u32.u64 %0, t; }" : "=r"(a) : "l"(p));
    return a;
}
__device__ __forceinline__ void cp16(uint32_t d, const void* s) {
    asm volatile("cp.async.ca.shared.global [%0], [%1], 16;" :: "r"(d), "l"(s) : "memory");
}
__device__ __forceinline__ uint32_t h2u(__half2 h) { return *reinterpret_cast<uint32_t*>(&h); }

__device__ __forceinline__ void mma16(float* d, uint32_t a0, uint32_t a1, uint32_t a2, uint32_t a3,
                                      uint32_t b0, uint32_t b1) {
    asm volatile(
        "mma.sync.aligned.m16n8k16.row.col.f32.f16.f16.f32 "
        "{%0,%1,%2,%3},{%4,%5,%6,%7},{%8,%9},{%0,%1,%2,%3};"
        : "+f"(d[0]), "+f"(d[1]), "+f"(d[2]), "+f"(d[3])
        : "r"(a0), "r"(a1), "r"(a2), "r"(a3), "r"(b0), "r"(b1));
}

// ---------------------------------------------------------------------------
// fp32 -> fp16 conversion (activations + weights)
// ---------------------------------------------------------------------------
__global__ void __launch_bounds__(256) convert_kernel(
    const float* __restrict__ q, const float* __restrict__ k, const float* __restrict__ v,
    const float* __restrict__ Wq, const float* __restrict__ Wk,
    const float* __restrict__ Wv, const float* __restrict__ Wo)
{
    const float* src; __half* dst; int n;
    switch (blockIdx.y) {
        case 0: src = q;  dst = c_q;  n = BB * SS * DD; break;
        case 1: src = k;  dst = c_k;  n = BB * SS * DD; break;
        case 2: src = v;  dst = c_v;  n = BB * SS * DD; break;
        case 3: src = Wq; dst = c_wq; n = DD * DD; break;
        case 4: src = Wk; dst = c_wk; n = DD * DD; break;
        case 5: src = Wv; dst = c_wv; n = DD * DD; break;
        default: src = Wo; dst = c_wo; n = DD * DD; break;
    }
    const int n4 = n >> 2;
    for (int i = blockIdx.x * 256 + threadIdx.x; i < n4; i += gridDim.x * 256) {
        float4 f = reinterpret_cast<const float4*>(src)[i];
        reinterpret_cast<__half2*>(dst)[2 * i]     = __floats2half2_rn(f.x, f.y);
        reinterpret_cast<__half2*>(dst)[2 * i + 1] = __floats2half2_rn(f.z, f.w);
    }
}

// ---------------------------------------------------------------------------
// fp16 GEMM: out = A[4096,1024] @ W[1024,1024] + bias
// 128x128 CTA tile, BK=32, 256 threads (8 warps 4Mx2N),
// 3-stage cp.async ring, one __syncthreads per K-tile, 2 CTAs/SM.
// ---------------------------------------------------------------------------
#define PALD 40       // A row pitch (halves)
#define PBLD 136      // B row pitch (halves)
#define A_STG 10240   // bytes per A stage (128 rows x 80B)
#define B_STG 8704    // bytes per B stage (32 rows x 272B)
#define B_BASE (3 * A_STG)                 // 30720
#define PROJ_SMEM_BYTES (B_BASE + 3 * B_STG)   // 56832 ; epilogue aliases 36864

using AF = wmma::fragment<wmma::matrix_a, 16, 16, 16, __half, wmma::row_major>;
using BF = wmma::fragment<wmma::matrix_b, 16, 16, 16, __half, wmma::row_major>;
using CF = wmma::fragment<wmma::accumulator, 16, 16, 16, float>;

__device__ __forceinline__ void gemm_fp16(const __half* __restrict__ A,
                                          const __half* __restrict__ Wm,
                                          const float* __restrict__ bias,
                                          void* __restrict__ outp, int half_head)
{
    extern __shared__ char dsm[];
    const uint32_t sb = smem_u32(dsm);
    const int tid  = threadIdx.x;
    const int warp = tid >> 5;
    const int lid  = tid & 31;
    const int wm   = warp >> 1;
    const int wn   = warp & 1;
    const int n0   = blockIdx.x * 128;
    const int m0   = blockIdx.y * 128;

    CF acc[2][4];
#pragma unroll
    for (int mf = 0; mf < 2; mf++)
#pragma unroll
        for (int nf = 0; nf < 4; nf++) wmma::fill_fragment(acc[mf][nf], 0.0f);

    auto issue = [&](int it) {
        const int kt = it * 32, stg = it % 3;
        const uint32_t ad = sb + stg * A_STG;
        const uint32_t bd = sb + B_BASE + stg * B_STG;
#pragma unroll
        for (int t = 0; t < 2; t++) {
            int id = tid + t * 256;                       // A: 128 rows x 4 x 16B
            cp16(ad + (id >> 2) * 80 + (id & 3) * 16,
                 A + (size_t)(m0 + (id >> 2)) * DD + kt + (id & 3) * 8);
        }
#pragma unroll
        for (int t = 0; t < 2; t++) {
            int id = tid + t * 256;                       // B: 32 rows x 16 x 16B
            cp16(bd + (id >> 4) * 272 + (id & 15) * 16,
                 Wm + (size_t)(kt + (id >> 4)) * DD + n0 + (id & 15) * 8);
        }
        asm volatile("cp.async.commit_group;" ::: "memory");
    };

    issue(0);
    issue(1);
    for (int it = 0; it < 32; it++) {
        if (it < 31) asm volatile("cp.async.wait_group 1;" ::: "memory");
        else         asm volatile("cp.async.wait_group 0;" ::: "memory");
        __syncthreads();
        if (it + 2 < 32) issue(it + 2);   // prefetch overlaps compute below

        const int stg = it % 3;
        const __half* Ab = reinterpret_cast<const __half*>(dsm) + stg * (A_STG / 2);
        const __half* Bb = reinterpret_cast<const __half*>(dsm + B_BASE) + stg * (B_STG / 2);
        AF a[2]; BF b[4];
#pragma unroll
        for (int kk = 0; kk < 32; kk += 16) {
#pragma unroll
            for (int mf = 0; mf < 2; mf++)
                wmma::load_matrix_sync(a[mf], Ab + (wm * 32 + mf * 16) * PALD + kk, PALD);
#pragma unroll
            for (int nf = 0; nf < 4; nf++)
                wmma::load_matrix_sync(b[nf], Bb + kk * PBLD + wn * 64 + nf * 16, PBLD);
#pragma unroll
            for (int mf = 0; mf < 2; mf++)
#pragma unroll
                for (int nf = 0; nf < 4; nf++)
                    wmma::mma_sync(acc[mf][nf], a[mf], b[nf], acc[mf][nf]);
        }
    }
    __syncthreads();

    // Epilogue: per-warp smem scratch (aliases ring buffers), 2 passes of 32 cols
    float* eps = reinterpret_cast<float*>(dsm) + warp * 1152;   // 32 x 36
    const int m = m0 + wm * 32 + lid;
#pragma unroll
    for (int pass = 0; pass < 2; pass++) {
        wmma::store_matrix_sync(eps,                acc[0][2 * pass],     36, wmma::mem_row_major);
        wmma::store_matrix_sync(eps + 16,           acc[0][2 * pass + 1], 36, wmma::mem_row_major);
        wmma::store_matrix_sync(eps + 16 * 36,      acc[1][2 * pass],     36, wmma::mem_row_major);
        wmma::store_matrix_sync(eps + 16 * 36 + 16, acc[1][2 * pass + 1], 36, wmma::mem_row_major);
        __syncwarp();
        const int nc0 = n0 + wn * 64 + pass * 32;
        if (half_head) {
            const int hh = nc0 >> 6, d = nc0 & 63;
            __half* dst = (__half*)outp +
                ((size_t)((m >> 11) * HH + hh) * SS + (m & 2047)) * DH + d;
#pragma unroll
            for (int c = 0; c < 32; c += 2) {
                float x = eps[lid * 36 + c]     + bias[nc0 + c];
                float y = eps[lid * 36 + c + 1] + bias[nc0 + c + 1];
                *reinterpret_cast<__half2*>(dst + c) = __floats2half2_rn(x, y);
            }
        } else {
            float* dst = (float*)outp + (size_t)m * DD + nc0;
#pragma unroll
            for (int c = 0; c < 32; c++) dst[c] = eps[lid * 36 + c] + bias[nc0 + c];
        }
        __syncwarp();
    }
}

__global__ void __launch_bounds__(256, 2) proj_qkv_kernel(
    const float* __restrict__ bq, const float* __restrict__ bk, const float* __restrict__ bv)
{
    const int z = blockIdx.z;
    const __half* A    = (z == 0) ? c_q  : (z == 1) ? c_k  : c_v;
    const __half* W    = (z == 0) ? c_wq : (z == 1) ? c_wk : c_wv;
    const float* bias  = (z == 0) ? bq   : (z == 1) ? bk   : bv;
    __half* out        = (z == 0) ? hq   : (z == 1) ? hk   : hv;
    gemm_fp16(A, W, bias, out, 1);
}

__global__ void __launch_bounds__(256, 2) proj_out_kernel(
    const float* __restrict__ bo, float* __restrict__ out)
{
    gemm_fp16(hctx, c_wo, bo, out, 0);
}

// ---------------------------------------------------------------------------
// Flash attention, fp16 mma.sync.m16n8k16, fully register-resident.
// CTA: 128 q rows (8 warps x 16), 64 keys/iter.
// ---------------------------------------------------------------------------
#define KLD 72
#define VLD 72

__global__ void __launch_bounds__(256, 2) attn_kernel(const float* __restrict__ mask)
{
    __shared__ __half Ks[64 * KLD];
    __shared__ __half Vt[64 * VLD];
    __shared__ float maskS[64];

    const int tid  = threadIdx.x;
    const int warp = tid >> 5;
    const int lane = tid & 31;
    const int g    = lane >> 2;
    const int t4   = lane & 3;
    const int wr0  = warp * 16;
    const int bh   = blockIdx.x;
    const int qt   = blockIdx.y;
    const int bb   = bh >> 4;
    const int hi   = bh & 15;

    const __half* Qg = hq + ((size_t)bh * SS + qt * 128 + wr0) * DH;
    const __half* Kg = hk + (size_t)bh * SS * DH;
    const __half* Vg = hv + (size_t)bh * SS * DH;

    uint32_t Qa[4][4];
#pragma unroll
    for (int kc = 0; kc < 4; kc++) {
        Qa[kc][0] = *reinterpret_cast<const uint32_t*>(Qg + (size_t)g * DH + kc * 16 + 2 * t4);
        Qa[kc][1] = *reinterpret_cast<const uint32_t*>(Qg + (size_t)(g + 8) * DH + kc * 16 + 2 * t4);
        Qa[kc][2] = *reinterpret_cast<const uint32_t*>(Qg + (size_t)g * DH + kc * 16 + 2 * t4 + 8);
        Qa[kc][3] = *reinterpret_cast<const uint32_t*>(Qg + (size_t)(g + 8) * DH + kc * 16 + 2 * t4 + 8);
    }

    float O[8][4];
#pragma unroll
    for (int d = 0; d < 8; d++) { O[d][0] = O[d][1] = O[d][2] = O[d][3] = 0.f; }
    float m0 = -1e30f, m1 = -1e30f, l0 = 0.f, l1 = 0.f;

    for (int kt0 = 0; kt0 < SS; kt0 += 64) {
        __syncthreads();
#pragma unroll
        for (int t = 0; t < 2; t++) {
            int idx = tid + t * 256;
            int r = idx >> 3, c = (idx & 7) * 8;
            *reinterpret_cast<uint4*>(Ks + r * KLD + c) =
                *reinterpret_cast<const uint4*>(Kg + (size_t)(kt0 + r) * DH + c);
            union { uint4 u; __half h[8]; } vv;
            vv.u = *reinterpret_cast<const uint4*>(Vg + (size_t)(kt0 + r) * DH + c);
#pragma unroll
            for (int j = 0; j < 8; j++) Vt[(c + j) * VLD + r] = vv.h[j];
        }
        if (tid < 64) maskS[tid] = mask[bb * SS + kt0 + tid] * (-1e9f);
        __syncthreads();

        float S[8][4];
#pragma unroll
        for (int j = 0; j < 8; j++) { S[j][0] = S[j][1] = S[j][2] = S[j][3] = 0.f; }
#pragma unroll
        for (int kc = 0; kc < 4; kc++) {
#pragma unroll
            for (int j = 0; j < 8; j++) {
                uint32_t b0 = *reinterpret_cast<const uint32_t*>(Ks + (8 * j + g) * KLD + kc * 16 + 2 * t4);
                uint32_t b1 = *reinterpret_cast<const uint32_t*>(Ks + (8 * j + g) * KLD + kc * 16 + 2 * t4 + 8);
                mma16(S[j], Qa[kc][0], Qa[kc][1], Qa[kc][2], Qa[kc][3], b0, b1);
            }
        }

        float mx0 = -1e30f, mx1 = -1e30f;
#pragma unroll
        for (int j = 0; j < 8; j++) {
            float k0 = maskS[8 * j + 2 * t4];
            float k1 = maskS[8 * j + 2 * t4 + 1];
            S[j][0] = S[j][0] * 0.125f + k0;
            S[j][1] = S[j][1] * 0.125f + k1;
            S[j][2] = S[j][2] * 0.125f + k0;
            S[j][3] = S[j][3] * 0.125f + k1;
            mx0 = fmaxf(mx0, fmaxf(S[j][0], S[j][1]));
            mx1 = fmaxf(mx1, fmaxf(S[j][2], S[j][3]));
        }
        mx0 = fmaxf(mx0, __shfl_xor_sync(0xffffffffu, mx0, 1));
        mx0 = fmaxf(mx0, __shfl_xor_sync(0xffffffffu, mx0, 2));
        mx1 = fmaxf(mx1, __shfl_xor_sync(0xffffffffu, mx1, 1));
        mx1 = fmaxf(mx1, __shfl_xor_sync(0xffffffffu, mx1, 2));
        const float nm0 = fmaxf(m0, mx0);
        const float nm1 = fmaxf(m1, mx1);
        const float al0 = __expf(m0 - nm0);
        const float al1 = __expf(m1 - nm1);
        m0 = nm0; m1 = nm1;
        float s0 = 0.f, s1 = 0.f;
#pragma unroll
        for (int j = 0; j < 8; j++) {
            S[j][0] = __expf(S[j][0] - nm0);
            S[j][1] = __expf(S[j][1] - nm0);
            S[j][2] = __expf(S[j][2] - nm1);
            S[j][3] = __expf(S[j][3] - nm1);
            s0 += S[j][0] + S[j][1];
            s1 += S[j][2] + S[j][3];
        }
        s0 += __shfl_xor_sync(0xffffffffu, s0, 1);
        s0 += __shfl_xor_sync(0xffffffffu, s0, 2);
        s1 += __shfl_xor_sync(0xffffffffu, s1, 1);
        s1 += __shfl_xor_sync(0xffffffffu, s1, 2);
        l0 = l0 * al0 + s0;
        l1 = l1 * al1 + s1;
#pragma unroll
        for (int d = 0; d < 8; d++) {
            O[d][0] *= al0; O[d][1] *= al0;
            O[d][2] *= al1; O[d][3] *= al1;
        }

#pragma unroll
        for (int kj = 0; kj < 4; kj++) {
            uint32_t a0 = h2u(__floats2half2_rn(S[2 * kj][0],     S[2 * kj][1]));
            uint32_t a1 = h2u(__floats2half2_rn(S[2 * kj][2],     S[2 * kj][3]));
            uint32_t a2 = h2u(__floats2half2_rn(S[2 * kj + 1][0], S[2 * kj + 1][1]));
            uint32_t a3 = h2u(__floats2half2_rn(S[2 * kj + 1][2], S[2 * kj + 1][3]));
#pragma unroll
            for (int d = 0; d < 8; d++) {
                uint32_t b0 = *reinterpret_cast<const uint32_t*>(Vt + (8 * d + g) * VLD + kj * 16 + 2 * t4);
                uint32_t b1 = *reinterpret_cast<const uint32_t*>(Vt + (8 * d + g) * VLD + kj * 16 + 2 * t4 + 8);
                mma16(O[d], a0, a1, a2, a3, b0, b1);
            }
        }
    }

    const float inv0 = 1.0f / l0;
    const float inv1 = 1.0f / l1;
    __half* base = hctx + ((size_t)(bb * SS + qt * 128 + wr0)) * DD + hi * DH;
#pragma unroll
    for (int d = 0; d < 8; d++) {
        *reinterpret_cast<__half2*>(base + (size_t)g * DD + 8 * d + 2 * t4) =
            __floats2half2_rn(O[d][0] * inv0, O[d][1] * inv0);
        *reinterpret_cast<__half2*>(base + (size_t)(g + 8) * DD + 8 * d + 2 * t4) =
            __floats2half2_rn(O[d][2] * inv1, O[d][3] * inv1);
    }
}

// ---------------------------------------------------------------------------
extern "C" void kernel_launch(void* const* d_in, const int* in_sizes, int n_in,
                              void* d_out, int out_size)
{
    const float* query = (const float*)d_in[0];
    const float* key   = (const float*)d_in[1];
    const float* value = (const float*)d_in[2];
    const float* mask  = (const float*)d_in[3];
    const float* Wq    = (const float*)d_in[4];
    const float* bq    = (const float*)d_in[5];
    const float* Wk    = (const float*)d_in[6];
    const float* bk    = (const float*)d_in[7];
    const float* Wv    = (const float*)d_in[8];
    const float* bv    = (const float*)d_in[9];
    const float* Wo    = (const float*)d_in[10];
    const float* bo    = (const float*)d_in[11];
    float* out = (float*)d_out;

    static int configured = 0;
    if (!configured) {
        cudaFuncSetAttribute(proj_qkv_kernel, cudaFuncAttributeMaxDynamicSharedMemorySize, PROJ_SMEM_BYTES);
        cudaFuncSetAttribute(proj_out_kernel, cudaFuncAttributeMaxDynamicSharedMemorySize, PROJ_SMEM_BYTES);
        configured = 1;
    }

    convert_kernel<<<dim3(512, 7), 256>>>(query, key, value, Wq, Wk, Wv, Wo);
    proj_qkv_kernel<<<dim3(8, 32, 3), 256, PROJ_SMEM_BYTES>>>(bq, bk, bv);
    attn_kernel<<<dim3(32, 16), 256>>>(mask);
    proj_out_kernel<<<dim3(8, 32), 256, PROJ_SMEM_BYTES>>>(bo, out);
}

// round 7
// speedup vs baseline: 4.8149x; 1.1889x over previous
#include <cuda_runtime.h>
#include <cuda_fp16.h>
#include <mma.h>
#include <cstdint>

using namespace nvcuda;

#define BB 2
#define SS 2048
#define DD 1024
#define HH 16
#define DH 64

// ---- scratch (__device__ globals; no allocations allowed) ----
__device__ __half c_q[BB * SS * DD], c_k[BB * SS * DD], c_v[BB * SS * DD];
__device__ __half c_wq[DD * DD], c_wk[DD * DD], c_wv[DD * DD], c_wo[DD * DD];
__device__ __half hq[BB * HH * SS * DH], hk[BB * HH * SS * DH], hv[BB * HH * SS * DH];
__device__ __half hctx[BB * SS * DD];

// ---------------- helpers ----------------
__device__ __forceinline__ uint32_t smem_u32(const void* p) {
    uint32_t a;
    asm("{ .reg .u64 t; cvta.to.shared.u64 t, %1; cvt.u32.u64 %0, t; }" : "=r"(a) : "l"(p));
    return a;
}
__device__ __forceinline__ void cp16(uint32_t d, const void* s) {
    asm volatile("cp.async.cg.shared.global [%0], [%1], 16;" :: "r"(d), "l"(s) : "memory");
}
__device__ __forceinline__ uint32_t h2u(__half2 h) { return *reinterpret_cast<uint32_t*>(&h); }

__device__ __forceinline__ void mma16(float* d, uint32_t a0, uint32_t a1, uint32_t a2, uint32_t a3,
                                      uint32_t b0, uint32_t b1) {
    asm volatile(
        "mma.sync.aligned.m16n8k16.row.col.f32.f16.f16.f32 "
        "{%0,%1,%2,%3},{%4,%5,%6,%7},{%8,%9},{%0,%1,%2,%3};"
        : "+f"(d[0]), "+f"(d[1]), "+f"(d[2]), "+f"(d[3])
        : "r"(a0), "r"(a1), "r"(a2), "r"(a3), "r"(b0), "r"(b1));
}
__device__ __forceinline__ void ldm4(uint32_t* r, uint32_t a) {
    asm volatile("ldmatrix.sync.aligned.m8n8.x4.shared.b16 {%0,%1,%2,%3}, [%4];"
        : "=r"(r[0]), "=r"(r[1]), "=r"(r[2]), "=r"(r[3]) : "r"(a));
}
__device__ __forceinline__ void ldm4t(uint32_t* r, uint32_t a) {
    asm volatile("ldmatrix.sync.aligned.m8n8.x4.trans.shared.b16 {%0,%1,%2,%3}, [%4];"
        : "=r"(r[0]), "=r"(r[1]), "=r"(r[2]), "=r"(r[3]) : "r"(a));
}

// ---------------------------------------------------------------------------
// fp32 -> fp16 conversion
// ---------------------------------------------------------------------------
__global__ void __launch_bounds__(256) convert_kernel(
    const float* __restrict__ q, const float* __restrict__ k, const float* __restrict__ v,
    const float* __restrict__ Wq, const float* __restrict__ Wk,
    const float* __restrict__ Wv, const float* __restrict__ Wo)
{
    const float* src; __half* dst; int n;
    switch (blockIdx.y) {
        case 0: src = q;  dst = c_q;  n = BB * SS * DD; break;
        case 1: src = k;  dst = c_k;  n = BB * SS * DD; break;
        case 2: src = v;  dst = c_v;  n = BB * SS * DD; break;
        case 3: src = Wq; dst = c_wq; n = DD * DD; break;
        case 4: src = Wk; dst = c_wk; n = DD * DD; break;
        case 5: src = Wv; dst = c_wv; n = DD * DD; break;
        default: src = Wo; dst = c_wo; n = DD * DD; break;
    }
    const int n4 = n >> 2;
    for (int i = blockIdx.x * 256 + threadIdx.x; i < n4; i += gridDim.x * 256) {
        float4 f = reinterpret_cast<const float4*>(src)[i];
        reinterpret_cast<__half2*>(dst)[2 * i]     = __floats2half2_rn(f.x, f.y);
        reinterpret_cast<__half2*>(dst)[2 * i + 1] = __floats2half2_rn(f.z, f.w);
    }
}

// ---------------------------------------------------------------------------
// fp16 GEMM: 128x128 tile, BK=32, 3-stage cp.async ring, 2 CTAs/SM.
// ---------------------------------------------------------------------------
#define PALD 40
#define PBLD 136
#define A_STG 10240
#define B_STG 8704
#define B_BASE (3 * A_STG)
#define PROJ_SMEM_BYTES (B_BASE + 3 * B_STG)   // 56832

using AF = wmma::fragment<wmma::matrix_a, 16, 16, 16, __half, wmma::row_major>;
using BF = wmma::fragment<wmma::matrix_b, 16, 16, 16, __half, wmma::row_major>;
using CF = wmma::fragment<wmma::accumulator, 16, 16, 16, float>;

__device__ __forceinline__ void gemm_fp16(const __half* __restrict__ A,
                                          const __half* __restrict__ Wm,
                                          const float* __restrict__ bias,
                                          void* __restrict__ outp, int half_head)
{
    extern __shared__ char dsm[];
    const uint32_t sb = smem_u32(dsm);
    const int tid  = threadIdx.x;
    const int warp = tid >> 5;
    const int lid  = tid & 31;
    const int wm   = warp >> 1;
    const int wn   = warp & 1;
    const int n0   = blockIdx.x * 128;
    const int m0   = blockIdx.y * 128;

    CF acc[2][4];
#pragma unroll
    for (int mf = 0; mf < 2; mf++)
#pragma unroll
        for (int nf = 0; nf < 4; nf++) wmma::fill_fragment(acc[mf][nf], 0.0f);

    auto issue = [&](int it) {
        const int kt = it * 32, stg = it % 3;
        const uint32_t ad = sb + stg * A_STG;
        const uint32_t bd = sb + B_BASE + stg * B_STG;
#pragma unroll
        for (int t = 0; t < 2; t++) {
            int id = tid + t * 256;
            cp16(ad + (id >> 2) * 80 + (id & 3) * 16,
                 A + (size_t)(m0 + (id >> 2)) * DD + kt + (id & 3) * 8);
        }
#pragma unroll
        for (int t = 0; t < 2; t++) {
            int id = tid + t * 256;
            cp16(bd + (id >> 4) * 272 + (id & 15) * 16,
                 Wm + (size_t)(kt + (id >> 4)) * DD + n0 + (id & 15) * 8);
        }
        asm volatile("cp.async.commit_group;" ::: "memory");
    };

    issue(0);
    issue(1);
    for (int it = 0; it < 32; it++) {
        if (it < 31) asm volatile("cp.async.wait_group 1;" ::: "memory");
        else         asm volatile("cp.async.wait_group 0;" ::: "memory");
        __syncthreads();
        if (it + 2 < 32) issue(it + 2);

        const int stg = it % 3;
        const __half* Ab = reinterpret_cast<const __half*>(dsm) + stg * (A_STG / 2);
        const __half* Bb = reinterpret_cast<const __half*>(dsm + B_BASE) + stg * (B_STG / 2);
        AF a[2]; BF b[4];
#pragma unroll
        for (int kk = 0; kk < 32; kk += 16) {
#pragma unroll
            for (int mf = 0; mf < 2; mf++)
                wmma::load_matrix_sync(a[mf], Ab + (wm * 32 + mf * 16) * PALD + kk, PALD);
#pragma unroll
            for (int nf = 0; nf < 4; nf++)
                wmma::load_matrix_sync(b[nf], Bb + kk * PBLD + wn * 64 + nf * 16, PBLD);
#pragma unroll
            for (int mf = 0; mf < 2; mf++)
#pragma unroll
                for (int nf = 0; nf < 4; nf++)
                    wmma::mma_sync(acc[mf][nf], a[mf], b[nf], acc[mf][nf]);
        }
    }
    __syncthreads();

    float* eps = reinterpret_cast<float*>(dsm) + warp * 1152;
    const int m = m0 + wm * 32 + lid;
#pragma unroll
    for (int pass = 0; pass < 2; pass++) {
        wmma::store_matrix_sync(eps,                acc[0][2 * pass],     36, wmma::mem_row_major);
        wmma::store_matrix_sync(eps + 16,           acc[0][2 * pass + 1], 36, wmma::mem_row_major);
        wmma::store_matrix_sync(eps + 16 * 36,      acc[1][2 * pass],     36, wmma::mem_row_major);
        wmma::store_matrix_sync(eps + 16 * 36 + 16, acc[1][2 * pass + 1], 36, wmma::mem_row_major);
        __syncwarp();
        const int nc0 = n0 + wn * 64 + pass * 32;
        if (half_head) {
            const int hh = nc0 >> 6, d = nc0 & 63;
            __half* dst = (__half*)outp +
                ((size_t)((m >> 11) * HH + hh) * SS + (m & 2047)) * DH + d;
#pragma unroll
            for (int c = 0; c < 32; c += 2) {
                float x = eps[lid * 36 + c]     + bias[nc0 + c];
                float y = eps[lid * 36 + c + 1] + bias[nc0 + c + 1];
                *reinterpret_cast<__half2*>(dst + c) = __floats2half2_rn(x, y);
            }
        } else {
            float* dst = (float*)outp + (size_t)m * DD + nc0;
#pragma unroll
            for (int c = 0; c < 32; c++) dst[c] = eps[lid * 36 + c] + bias[nc0 + c];
        }
        __syncwarp();
    }
}

__global__ void __launch_bounds__(256, 2) proj_qkv_kernel(
    const float* __restrict__ bq, const float* __restrict__ bk, const float* __restrict__ bv)
{
    const int z = blockIdx.z;
    const __half* A    = (z == 0) ? c_q  : (z == 1) ? c_k  : c_v;
    const __half* W    = (z == 0) ? c_wq : (z == 1) ? c_wk : c_wv;
    const float* bias  = (z == 0) ? bq   : (z == 1) ? bk   : bv;
    __half* out        = (z == 0) ? hq   : (z == 1) ? hk   : hv;
    gemm_fp16(A, W, bias, out, 1);
}

__global__ void __launch_bounds__(256, 2) proj_out_kernel(
    const float* __restrict__ bo, float* __restrict__ out)
{
    gemm_fp16(hctx, c_wo, bo, out, 0);
}

// ---------------------------------------------------------------------------
// Flash attention, fp16 mma.sync.m16n8k16 + ldmatrix B-fragments.
// CTA: 128 q rows (8 warps x 16), 64 keys/iter. K,V both row-major in smem.
// ---------------------------------------------------------------------------
#define KLD 72
#define VLD 72

__global__ void __launch_bounds__(256, 2) attn_kernel(const float* __restrict__ mask)
{
    __shared__ __half Ks[64 * KLD];
    __shared__ __half Vs[64 * VLD];
    __shared__ float maskS[64];

    const int tid  = threadIdx.x;
    const int warp = tid >> 5;
    const int lane = tid & 31;
    const int g    = lane >> 2;
    const int t4   = lane & 3;
    const int wr0  = warp * 16;
    const int bh   = blockIdx.x;
    const int qt   = blockIdx.y;
    const int bb   = bh >> 4;
    const int hi   = bh & 15;

    const __half* Qg = hq + ((size_t)bh * SS + qt * 128 + wr0) * DH;
    const __half* Kg = hk + (size_t)bh * SS * DH;
    const __half* Vg = hv + (size_t)bh * SS * DH;

    // Q fragments (reused across all key tiles)
    uint32_t Qa[4][4];
#pragma unroll
    for (int kc = 0; kc < 4; kc++) {
        Qa[kc][0] = *reinterpret_cast<const uint32_t*>(Qg + (size_t)g * DH + kc * 16 + 2 * t4);
        Qa[kc][1] = *reinterpret_cast<const uint32_t*>(Qg + (size_t)(g + 8) * DH + kc * 16 + 2 * t4);
        Qa[kc][2] = *reinterpret_cast<const uint32_t*>(Qg + (size_t)g * DH + kc * 16 + 2 * t4 + 8);
        Qa[kc][3] = *reinterpret_cast<const uint32_t*>(Qg + (size_t)(g + 8) * DH + kc * 16 + 2 * t4 + 8);
    }

    // ldmatrix lane address bases (constant across tiles; smem is static)
    // K (non-trans): matrices {b0(j),b1(j),b0(j+1),b1(j+1)} for jp -> j=2jp,2jp+1
    const int krow = (lane & 7) + ((lane >> 4) & 1) * 8;
    const int kcol = ((lane >> 3) & 1) * 8;
    uint32_t kaddr[4];
#pragma unroll
    for (int jp = 0; jp < 4; jp++)
        kaddr[jp] = smem_u32(Ks + (16 * jp + krow) * KLD + kcol);
    // V (trans): matrices {b0(d),b1(d),b0(d+1),b1(d+1)} for dp -> d=2dp,2dp+1
    const int vrow = (lane & 7) + ((lane >> 3) & 1) * 8;
    const int vcol = ((lane >> 4) & 1) * 8;
    uint32_t vaddr[4];
#pragma unroll
    for (int dp = 0; dp < 4; dp++)
        vaddr[dp] = smem_u32(Vs + vrow * VLD + 16 * dp + vcol);

    float O[8][4];
#pragma unroll
    for (int d = 0; d < 8; d++) { O[d][0] = O[d][1] = O[d][2] = O[d][3] = 0.f; }
    float m0 = -1e30f, m1 = -1e30f, l0 = 0.f, l1 = 0.f;

    for (int kt0 = 0; kt0 < SS; kt0 += 64) {
        __syncthreads();
#pragma unroll
        for (int t = 0; t < 2; t++) {
            int idx = tid + t * 256;
            int r = idx >> 3, c = (idx & 7) * 8;
            *reinterpret_cast<uint4*>(Ks + r * KLD + c) =
                *reinterpret_cast<const uint4*>(Kg + (size_t)(kt0 + r) * DH + c);
            *reinterpret_cast<uint4*>(Vs + r * VLD + c) =
                *reinterpret_cast<const uint4*>(Vg + (size_t)(kt0 + r) * DH + c);
        }
        if (tid < 64) maskS[tid] = mask[bb * SS + kt0 + tid] * (-1e9f);
        __syncthreads();

        // S = Q K^T
        float S[8][4];
#pragma unroll
        for (int j = 0; j < 8; j++) { S[j][0] = S[j][1] = S[j][2] = S[j][3] = 0.f; }
#pragma unroll
        for (int kc = 0; kc < 4; kc++) {
#pragma unroll
            for (int jp = 0; jp < 4; jp++) {
                uint32_t br[4];
                ldm4(br, kaddr[jp] + kc * 32);   // +16 halves per kc
                mma16(S[2 * jp],     Qa[kc][0], Qa[kc][1], Qa[kc][2], Qa[kc][3], br[0], br[1]);
                mma16(S[2 * jp + 1], Qa[kc][0], Qa[kc][1], Qa[kc][2], Qa[kc][3], br[2], br[3]);
            }
        }

        // online softmax on fragments
        float mx0 = -1e30f, mx1 = -1e30f;
#pragma unroll
        for (int j = 0; j < 8; j++) {
            float k0 = maskS[8 * j + 2 * t4];
            float k1 = maskS[8 * j + 2 * t4 + 1];
            S[j][0] = S[j][0] * 0.125f + k0;
            S[j][1] = S[j][1] * 0.125f + k1;
            S[j][2] = S[j][2] * 0.125f + k0;
            S[j][3] = S[j][3] * 0.125f + k1;
            mx0 = fmaxf(mx0, fmaxf(S[j][0], S[j][1]));
            mx1 = fmaxf(mx1, fmaxf(S[j][2], S[j][3]));
        }
        mx0 = fmaxf(mx0, __shfl_xor_sync(0xffffffffu, mx0, 1));
        mx0 = fmaxf(mx0, __shfl_xor_sync(0xffffffffu, mx0, 2));
        mx1 = fmaxf(mx1, __shfl_xor_sync(0xffffffffu, mx1, 1));
        mx1 = fmaxf(mx1, __shfl_xor_sync(0xffffffffu, mx1, 2));
        const float nm0 = fmaxf(m0, mx0);
        const float nm1 = fmaxf(m1, mx1);
        const float al0 = __expf(m0 - nm0);
        const float al1 = __expf(m1 - nm1);
        m0 = nm0; m1 = nm1;
        float s0 = 0.f, s1 = 0.f;
#pragma unroll
        for (int j = 0; j < 8; j++) {
            S[j][0] = __expf(S[j][0] - nm0);
            S[j][1] = __expf(S[j][1] - nm0);
            S[j][2] = __expf(S[j][2] - nm1);
            S[j][3] = __expf(S[j][3] - nm1);
            s0 += S[j][0] + S[j][1];
            s1 += S[j][2] + S[j][3];
        }
        s0 += __shfl_xor_sync(0xffffffffu, s0, 1);
        s0 += __shfl_xor_sync(0xffffffffu, s0, 2);
        s1 += __shfl_xor_sync(0xffffffffu, s1, 1);
        s1 += __shfl_xor_sync(0xffffffffu, s1, 2);
        l0 = l0 * al0 + s0;
        l1 = l1 * al1 + s1;
#pragma unroll
        for (int d = 0; d < 8; d++) {
            O[d][0] *= al0; O[d][1] *= al0;
            O[d][2] *= al1; O[d][3] *= al1;
        }

        // O += P V  (V row-major; trans-ldmatrix gives col-major B frags)
#pragma unroll
        for (int kj = 0; kj < 4; kj++) {
            uint32_t a0 = h2u(__floats2half2_rn(S[2 * kj][0],     S[2 * kj][1]));
            uint32_t a1 = h2u(__floats2half2_rn(S[2 * kj][2],     S[2 * kj][3]));
            uint32_t a2 = h2u(__floats2half2_rn(S[2 * kj + 1][0], S[2 * kj + 1][1]));
            uint32_t a3 = h2u(__floats2half2_rn(S[2 * kj + 1][2], S[2 * kj + 1][3]));
#pragma unroll
            for (int dp = 0; dp < 4; dp++) {
                uint32_t br[4];
                ldm4t(br, vaddr[dp] + kj * (16 * VLD * 2));
                mma16(O[2 * dp],     a0, a1, a2, a3, br[0], br[1]);
                mma16(O[2 * dp + 1], a0, a1, a2, a3, br[2], br[3]);
            }
        }
    }

    const float inv0 = 1.0f / l0;
    const float inv1 = 1.0f / l1;
    __half* base = hctx + ((size_t)(bb * SS + qt * 128 + wr0)) * DD + hi * DH;
#pragma unroll
    for (int d = 0; d < 8; d++) {
        *reinterpret_cast<__half2*>(base + (size_t)g * DD + 8 * d + 2 * t4) =
            __floats2half2_rn(O[d][0] * inv0, O[d][1] * inv0);
        *reinterpret_cast<__half2*>(base + (size_t)(g + 8) * DD + 8 * d + 2 * t4) =
            __floats2half2_rn(O[d][2] * inv1, O[d][3] * inv1);
    }
}

// ---------------------------------------------------------------------------
extern "C" void kernel_launch(void* const* d_in, const int* in_sizes, int n_in,
                              void* d_out, int out_size)
{
    const float* query = (const float*)d_in[0];
    const float* key   = (const float*)d_in[1];
    const float* value = (const float*)d_in[2];
    const float* mask  = (const float*)d_in[3];
    const float* Wq    = (const float*)d_in[4];
    const float* bq    = (const float*)d_in[5];
    const float* Wk    = (const float*)d_in[6];
    const float* bk    = (const float*)d_in[7];
    const float* Wv    = (const float*)d_in[8];
    const float* bv    = (const float*)d_in[9];
    const float* Wo    = (const float*)d_in[10];
    const float* bo    = (const float*)d_in[11];
    float* out = (float*)d_out;

    static int configured = 0;
    if (!configured) {
        cudaFuncSetAttribute(proj_qkv_kernel, cudaFuncAttributeMaxDynamicSharedMemorySize, PROJ_SMEM_BYTES);
        cudaFuncSetAttribute(proj_out_kernel, cudaFuncAttributeMaxDynamicSharedMemorySize, PROJ_SMEM_BYTES);
        configured = 1;
    }

    convert_kernel<<<dim3(512, 7), 256>>>(query, key, value, Wq, Wk, Wv, Wo);
    proj_qkv_kernel<<<dim3(8, 32, 3), 256, PROJ_SMEM_BYTES>>>(bq, bk, bv);
    attn_kernel<<<dim3(32, 16), 256>>>(mask);
    proj_out_kernel<<<dim3(8, 32), 256, PROJ_SMEM_BYTES>>>(bo, out);
}

// round 8
// speedup vs baseline: 5.1479x; 1.0692x over previous
#include <cuda_runtime.h>
#include <cuda_fp16.h>
#include <mma.h>
#include <cstdint>

using namespace nvcuda;

#define BB 2
#define SS 2048
#define DD 1024
#define HH 16
#define DH 64

// ---- scratch (__device__ globals; no allocations allowed) ----
__device__ __half c_q[BB * SS * DD], c_k[BB * SS * DD], c_v[BB * SS * DD];
__device__ __half c_wq[DD * DD], c_wk[DD * DD], c_wv[DD * DD], c_wo[DD * DD];
__device__ __half hq[BB * HH * SS * DH], hk[BB * HH * SS * DH], hv[BB * HH * SS * DH];
__device__ __half hctx[BB * SS * DD];

// ---------------- helpers ----------------
__device__ __forceinline__ uint32_t smem_u32(const void* p) {
    uint32_t a;
    asm("{ .reg .u64 t; cvta.to.shared.u64 t, %1; cvt.u32.u64 %0, t; }" : "=r"(a) : "l"(p));
    return a;
}
__device__ __forceinline__ void cp16(uint32_t d, const void* s) {
    asm volatile("cp.async.cg.shared.global [%0], [%1], 16;" :: "r"(d), "l"(s) : "memory");
}
__device__ __forceinline__ uint32_t h2u(__half2 h) { return *reinterpret_cast<uint32_t*>(&h); }

__device__ __forceinline__ void mma16(float* d, uint32_t a0, uint32_t a1, uint32_t a2, uint32_t a3,
                                      uint32_t b0, uint32_t b1) {
    asm volatile(
        "mma.sync.aligned.m16n8k16.row.col.f32.f16.f16.f32 "
        "{%0,%1,%2,%3},{%4,%5,%6,%7},{%8,%9},{%0,%1,%2,%3};"
        : "+f"(d[0]), "+f"(d[1]), "+f"(d[2]), "+f"(d[3])
        : "r"(a0), "r"(a1), "r"(a2), "r"(a3), "r"(b0), "r"(b1));
}
__device__ __forceinline__ void ldm4(uint32_t* r, uint32_t a) {
    asm volatile("ldmatrix.sync.aligned.m8n8.x4.shared.b16 {%0,%1,%2,%3}, [%4];"
        : "=r"(r[0]), "=r"(r[1]), "=r"(r[2]), "=r"(r[3]) : "r"(a));
}
__device__ __forceinline__ void ldm4t(uint32_t* r, uint32_t a) {
    asm volatile("ldmatrix.sync.aligned.m8n8.x4.trans.shared.b16 {%0,%1,%2,%3}, [%4];"
        : "=r"(r[0]), "=r"(r[1]), "=r"(r[2]), "=r"(r[3]) : "r"(a));
}

// ---------------------------------------------------------------------------
// fp32 -> fp16 conversion
// ---------------------------------------------------------------------------
__global__ void __launch_bounds__(256) convert_kernel(
    const float* __restrict__ q, const float* __restrict__ k, const float* __restrict__ v,
    const float* __restrict__ Wq, const float* __restrict__ Wk,
    const float* __restrict__ Wv, const float* __restrict__ Wo)
{
    const float* src; __half* dst; int n;
    switch (blockIdx.y) {
        case 0: src = q;  dst = c_q;  n = BB * SS * DD; break;
        case 1: src = k;  dst = c_k;  n = BB * SS * DD; break;
        case 2: src = v;  dst = c_v;  n = BB * SS * DD; break;
        case 3: src = Wq; dst = c_wq; n = DD * DD; break;
        case 4: src = Wk; dst = c_wk; n = DD * DD; break;
        case 5: src = Wv; dst = c_wv; n = DD * DD; break;
        default: src = Wo; dst = c_wo; n = DD * DD; break;
    }
    const int n4 = n >> 2;
    for (int i = blockIdx.x * 256 + threadIdx.x; i < n4; i += gridDim.x * 256) {
        float4 f = reinterpret_cast<const float4*>(src)[i];
        reinterpret_cast<__half2*>(dst)[2 * i]     = __floats2half2_rn(f.x, f.y);
        reinterpret_cast<__half2*>(dst)[2 * i + 1] = __floats2half2_rn(f.z, f.w);
    }
}

// ---------------------------------------------------------------------------
// fp16 GEMM: 128x128 CTA tile, BK=32, 128 threads (4 warps, 2Mx2N, warp tile
// 64x64), 3-stage cp.async ring, 2 CTAs/SM via __launch_bounds__(128,2).
// ---------------------------------------------------------------------------
#define PALD 40
#define PBLD 136
#define A_STG 10240
#define B_STG 8704
#define B_BASE (3 * A_STG)
#define PROJ_SMEM_BYTES (B_BASE + 3 * B_STG)   // 56832

using AF = wmma::fragment<wmma::matrix_a, 16, 16, 16, __half, wmma::row_major>;
using BF = wmma::fragment<wmma::matrix_b, 16, 16, 16, __half, wmma::row_major>;
using CF = wmma::fragment<wmma::accumulator, 16, 16, 16, float>;

__device__ __forceinline__ void gemm_fp16(const __half* __restrict__ A,
                                          const __half* __restrict__ Wm,
                                          const float* __restrict__ bias,
                                          void* __restrict__ outp, int half_head)
{
    extern __shared__ char dsm[];
    const uint32_t sb = smem_u32(dsm);
    const int tid  = threadIdx.x;
    const int warp = tid >> 5;
    const int lid  = tid & 31;
    const int wm   = warp >> 1;    // 0..1
    const int wn   = warp & 1;     // 0..1
    const int n0   = blockIdx.x * 128;
    const int m0   = blockIdx.y * 128;

    CF acc[4][4];
#pragma unroll
    for (int mf = 0; mf < 4; mf++)
#pragma unroll
        for (int nf = 0; nf < 4; nf++) wmma::fill_fragment(acc[mf][nf], 0.0f);

    auto issue = [&](int it) {
        const int kt = it * 32, stg = it % 3;
        const uint32_t ad = sb + stg * A_STG;
        const uint32_t bd = sb + B_BASE + stg * B_STG;
#pragma unroll
        for (int t = 0; t < 4; t++) {
            int id = tid + t * 128;                 // A: 128 rows x 4 x 16B
            cp16(ad + (id >> 2) * 80 + (id & 3) * 16,
                 A + (size_t)(m0 + (id >> 2)) * DD + kt + (id & 3) * 8);
        }
#pragma unroll
        for (int t = 0; t < 4; t++) {
            int id = tid + t * 128;                 // B: 32 rows x 16 x 16B
            cp16(bd + (id >> 4) * 272 + (id & 15) * 16,
                 Wm + (size_t)(kt + (id >> 4)) * DD + n0 + (id & 15) * 8);
        }
        asm volatile("cp.async.commit_group;" ::: "memory");
    };

    issue(0);
    issue(1);
    for (int it = 0; it < 32; it++) {
        if (it < 31) asm volatile("cp.async.wait_group 1;" ::: "memory");
        else         asm volatile("cp.async.wait_group 0;" ::: "memory");
        __syncthreads();
        if (it + 2 < 32) issue(it + 2);

        const int stg = it % 3;
        const __half* Ab = reinterpret_cast<const __half*>(dsm) + stg * (A_STG / 2);
        const __half* Bb = reinterpret_cast<const __half*>(dsm + B_BASE) + stg * (B_STG / 2);
        AF a[4]; BF b;
#pragma unroll
        for (int kk = 0; kk < 32; kk += 16) {
#pragma unroll
            for (int mf = 0; mf < 4; mf++)
                wmma::load_matrix_sync(a[mf], Ab + (wm * 64 + mf * 16) * PALD + kk, PALD);
#pragma unroll
            for (int nf = 0; nf < 4; nf++) {
                wmma::load_matrix_sync(b, Bb + kk * PBLD + wn * 64 + nf * 16, PBLD);
#pragma unroll
                for (int mf = 0; mf < 4; mf++)
                    wmma::mma_sync(acc[mf][nf], a[mf], b, acc[mf][nf]);
            }
        }
    }
    __syncthreads();

    // Epilogue: per-warp smem scratch (aliases ring), 8 passes of 32 rows x 16 cols
    float* eps = reinterpret_cast<float*>(dsm) + warp * 640;   // 32 x 20 floats
#pragma unroll
    for (int nf = 0; nf < 4; nf++) {
#pragma unroll
        for (int mfp = 0; mfp < 2; mfp++) {
            wmma::store_matrix_sync(eps,            acc[2 * mfp][nf],     20, wmma::mem_row_major);
            wmma::store_matrix_sync(eps + 16 * 20,  acc[2 * mfp + 1][nf], 20, wmma::mem_row_major);
            __syncwarp();
            const int m   = m0 + wm * 64 + mfp * 32 + lid;
            const int nc0 = n0 + wn * 64 + nf * 16;
            if (half_head) {
                const int hh = nc0 >> 6, d = nc0 & 63;
                __half* dst = (__half*)outp +
                    ((size_t)((m >> 11) * HH + hh) * SS + (m & 2047)) * DH + d;
#pragma unroll
                for (int c = 0; c < 16; c += 2) {
                    float x = eps[lid * 20 + c]     + bias[nc0 + c];
                    float y = eps[lid * 20 + c + 1] + bias[nc0 + c + 1];
                    *reinterpret_cast<__half2*>(dst + c) = __floats2half2_rn(x, y);
                }
            } else {
                float* dst = (float*)outp + (size_t)m * DD + nc0;
#pragma unroll
                for (int c = 0; c < 16; c++) dst[c] = eps[lid * 20 + c] + bias[nc0 + c];
            }
            __syncwarp();
        }
    }
}

__global__ void __launch_bounds__(128, 2) proj_qkv_kernel(
    const float* __restrict__ bq, const float* __restrict__ bk, const float* __restrict__ bv)
{
    const int z = blockIdx.z;
    const __half* A    = (z == 0) ? c_q  : (z == 1) ? c_k  : c_v;
    const __half* W    = (z == 0) ? c_wq : (z == 1) ? c_wk : c_wv;
    const float* bias  = (z == 0) ? bq   : (z == 1) ? bk   : bv;
    __half* out        = (z == 0) ? hq   : (z == 1) ? hk   : hv;
    gemm_fp16(A, W, bias, out, 1);
}

__global__ void __launch_bounds__(128, 2) proj_out_kernel(
    const float* __restrict__ bo, float* __restrict__ out)
{
    gemm_fp16(hctx, c_wo, bo, out, 0);
}

// ---------------------------------------------------------------------------
// Flash attention, fp16 mma.sync.m16n8k16 + ldmatrix B-fragments. (unchanged)
// ---------------------------------------------------------------------------
#define KLD 72
#define VLD 72

__global__ void __launch_bounds__(256, 2) attn_kernel(const float* __restrict__ mask)
{
    __shared__ __half Ks[64 * KLD];
    __shared__ __half Vs[64 * VLD];
    __shared__ float maskS[64];

    const int tid  = threadIdx.x;
    const int warp = tid >> 5;
    const int lane = tid & 31;
    const int g    = lane >> 2;
    const int t4   = lane & 3;
    const int wr0  = warp * 16;
    const int bh   = blockIdx.x;
    const int qt   = blockIdx.y;
    const int bb   = bh >> 4;
    const int hi   = bh & 15;

    const __half* Qg = hq + ((size_t)bh * SS + qt * 128 + wr0) * DH;
    const __half* Kg = hk + (size_t)bh * SS * DH;
    const __half* Vg = hv + (size_t)bh * SS * DH;

    uint32_t Qa[4][4];
#pragma unroll
    for (int kc = 0; kc < 4; kc++) {
        Qa[kc][0] = *reinterpret_cast<const uint32_t*>(Qg + (size_t)g * DH + kc * 16 + 2 * t4);
        Qa[kc][1] = *reinterpret_cast<const uint32_t*>(Qg + (size_t)(g + 8) * DH + kc * 16 + 2 * t4);
        Qa[kc][2] = *reinterpret_cast<const uint32_t*>(Qg + (size_t)g * DH + kc * 16 + 2 * t4 + 8);
        Qa[kc][3] = *reinterpret_cast<const uint32_t*>(Qg + (size_t)(g + 8) * DH + kc * 16 + 2 * t4 + 8);
    }

    const int krow = (lane & 7) + ((lane >> 4) & 1) * 8;
    const int kcol = ((lane >> 3) & 1) * 8;
    uint32_t kaddr[4];
#pragma unroll
    for (int jp = 0; jp < 4; jp++)
        kaddr[jp] = smem_u32(Ks + (16 * jp + krow) * KLD + kcol);
    const int vrow = (lane & 7) + ((lane >> 3) & 1) * 8;
    const int vcol = ((lane >> 4) & 1) * 8;
    uint32_t vaddr[4];
#pragma unroll
    for (int dp = 0; dp < 4; dp++)
        vaddr[dp] = smem_u32(Vs + vrow * VLD + 16 * dp + vcol);

    float O[8][4];
#pragma unroll
    for (int d = 0; d < 8; d++) { O[d][0] = O[d][1] = O[d][2] = O[d][3] = 0.f; }
    float m0 = -1e30f, m1 = -1e30f, l0 = 0.f, l1 = 0.f;

    for (int kt0 = 0; kt0 < SS; kt0 += 64) {
        __syncthreads();
#pragma unroll
        for (int t = 0; t < 2; t++) {
            int idx = tid + t * 256;
            int r = idx >> 3, c = (idx & 7) * 8;
            *reinterpret_cast<uint4*>(Ks + r * KLD + c) =
                *reinterpret_cast<const uint4*>(Kg + (size_t)(kt0 + r) * DH + c);
            *reinterpret_cast<uint4*>(Vs + r * VLD + c) =
                *reinterpret_cast<const uint4*>(Vg + (size_t)(kt0 + r) * DH + c);
        }
        if (tid < 64) maskS[tid] = mask[bb * SS + kt0 + tid] * (-1e9f);
        __syncthreads();

        float S[8][4];
#pragma unroll
        for (int j = 0; j < 8; j++) { S[j][0] = S[j][1] = S[j][2] = S[j][3] = 0.f; }
#pragma unroll
        for (int kc = 0; kc < 4; kc++) {
#pragma unroll
            for (int jp = 0; jp < 4; jp++) {
                uint32_t br[4];
                ldm4(br, kaddr[jp] + kc * 32);
                mma16(S[2 * jp],     Qa[kc][0], Qa[kc][1], Qa[kc][2], Qa[kc][3], br[0], br[1]);
                mma16(S[2 * jp + 1], Qa[kc][0], Qa[kc][1], Qa[kc][2], Qa[kc][3], br[2], br[3]);
            }
        }

        float mx0 = -1e30f, mx1 = -1e30f;
#pragma unroll
        for (int j = 0; j < 8; j++) {
            float k0 = maskS[8 * j + 2 * t4];
            float k1 = maskS[8 * j + 2 * t4 + 1];
            S[j][0] = S[j][0] * 0.125f + k0;
            S[j][1] = S[j][1] * 0.125f + k1;
            S[j][2] = S[j][2] * 0.125f + k0;
            S[j][3] = S[j][3] * 0.125f + k1;
            mx0 = fmaxf(mx0, fmaxf(S[j][0], S[j][1]));
            mx1 = fmaxf(mx1, fmaxf(S[j][2], S[j][3]));
        }
        mx0 = fmaxf(mx0, __shfl_xor_sync(0xffffffffu, mx0, 1));
        mx0 = fmaxf(mx0, __shfl_xor_sync(0xffffffffu, mx0, 2));
        mx1 = fmaxf(mx1, __shfl_xor_sync(0xffffffffu, mx1, 1));
        mx1 = fmaxf(mx1, __shfl_xor_sync(0xffffffffu, mx1, 2));
        const float nm0 = fmaxf(m0, mx0);
        const float nm1 = fmaxf(m1, mx1);
        const float al0 = __expf(m0 - nm0);
        const float al1 = __expf(m1 - nm1);
        m0 = nm0; m1 = nm1;
        float s0 = 0.f, s1 = 0.f;
#pragma unroll
        for (int j = 0; j < 8; j++) {
            S[j][0] = __expf(S[j][0] - nm0);
            S[j][1] = __expf(S[j][1] - nm0);
            S[j][2] = __expf(S[j][2] - nm1);
            S[j][3] = __expf(S[j][3] - nm1);
            s0 += S[j][0] + S[j][1];
            s1 += S[j][2] + S[j][3];
        }
        s0 += __shfl_xor_sync(0xffffffffu, s0, 1);
        s0 += __shfl_xor_sync(0xffffffffu, s0, 2);
        s1 += __shfl_xor_sync(0xffffffffu, s1, 1);
        s1 += __shfl_xor_sync(0xffffffffu, s1, 2);
        l0 = l0 * al0 + s0;
        l1 = l1 * al1 + s1;
#pragma unroll
        for (int d = 0; d < 8; d++) {
            O[d][0] *= al0; O[d][1] *= al0;
            O[d][2] *= al1; O[d][3] *= al1;
        }

#pragma unroll
        for (int kj = 0; kj < 4; kj++) {
            uint32_t a0 = h2u(__floats2half2_rn(S[2 * kj][0],     S[2 * kj][1]));
            uint32_t a1 = h2u(__floats2half2_rn(S[2 * kj][2],     S[2 * kj][3]));
            uint32_t a2 = h2u(__floats2half2_rn(S[2 * kj + 1][0], S[2 * kj + 1][1]));
            uint32_t a3 = h2u(__floats2half2_rn(S[2 * kj + 1][2], S[2 * kj + 1][3]));
#pragma unroll
            for (int dp = 0; dp < 4; dp++) {
                uint32_t br[4];
                ldm4t(br, vaddr[dp] + kj * (16 * VLD * 2));
                mma16(O[2 * dp],     a0, a1, a2, a3, br[0], br[1]);
                mma16(O[2 * dp + 1], a0, a1, a2, a3, br[2], br[3]);
            }
        }
    }

    const float inv0 = 1.0f / l0;
    const float inv1 = 1.0f / l1;
    __half* base = hctx + ((size_t)(bb * SS + qt * 128 + wr0)) * DD + hi * DH;
#pragma unroll
    for (int d = 0; d < 8; d++) {
        *reinterpret_cast<__half2*>(base + (size_t)g * DD + 8 * d + 2 * t4) =
            __floats2half2_rn(O[d][0] * inv0, O[d][1] * inv0);
        *reinterpret_cast<__half2*>(base + (size_t)(g + 8) * DD + 8 * d + 2 * t4) =
            __floats2half2_rn(O[d][2] * inv1, O[d][3] * inv1);
    }
}

// ---------------------------------------------------------------------------
extern "C" void kernel_launch(void* const* d_in, const int* in_sizes, int n_in,
                              void* d_out, int out_size)
{
    const float* query = (const float*)d_in[0];
    const float* key   = (const float*)d_in[1];
    const float* value = (const float*)d_in[2];
    const float* mask  = (const float*)d_in[3];
    const float* Wq    = (const float*)d_in[4];
    const float* bq    = (const float*)d_in[5];
    const float* Wk    = (const float*)d_in[6];
    const float* bk    = (const float*)d_in[7];
    const float* Wv    = (const float*)d_in[8];
    const float* bv    = (const float*)d_in[9];
    const float* Wo    = (const float*)d_in[10];
    const float* bo    = (const float*)d_in[11];
    float* out = (float*)d_out;

    static int configured = 0;
    if (!configured) {
        cudaFuncSetAttribute(proj_qkv_kernel, cudaFuncAttributeMaxDynamicSharedMemorySize, PROJ_SMEM_BYTES);
        cudaFuncSetAttribute(proj_out_kernel, cudaFuncAttributeMaxDynamicSharedMemorySize, PROJ_SMEM_BYTES);
        configured = 1;
    }

    convert_kernel<<<dim3(512, 7), 256>>>(query, key, value, Wq, Wk, Wv, Wo);
    proj_qkv_kernel<<<dim3(8, 32, 3), 128, PROJ_SMEM_BYTES>>>(bq, bk, bv);
    attn_kernel<<<dim3(32, 16), 256>>>(mask);
    proj_out_kernel<<<dim3(8, 32), 128, PROJ_SMEM_BYTES>>>(bo, out);
}

// round 9
// speedup vs baseline: 5.2403x; 1.0180x over previous
#include <cuda_runtime.h>
#include <cuda_fp16.h>
#include <mma.h>
#include <cstdint>

using namespace nvcuda;

#define BB 2
#define SS 2048
#define DD 1024
#define HH 16
#define DH 64

// ---- scratch (__device__ globals; no allocations allowed) ----
__device__ __half c_q[BB * SS * DD], c_k[BB * SS * DD], c_v[BB * SS * DD];
__device__ __half c_wq[DD * DD], c_wk[DD * DD], c_wv[DD * DD], c_wo[DD * DD];
__device__ __half hq[BB * HH * SS * DH], hk[BB * HH * SS * DH], hv[BB * HH * SS * DH];
__device__ __half hctx[BB * SS * DD];

// ---------------- helpers ----------------
__device__ __forceinline__ uint32_t smem_u32(const void* p) {
    uint32_t a;
    asm("{ .reg .u64 t; cvta.to.shared.u64 t, %1; cvt.u32.u64 %0, t; }" : "=r"(a) : "l"(p));
    return a;
}
__device__ __forceinline__ void cp16(uint32_t d, const void* s) {
    asm volatile("cp.async.cg.shared.global [%0], [%1], 16;" :: "r"(d), "l"(s) : "memory");
}
__device__ __forceinline__ uint32_t h2u(__half2 h) { return *reinterpret_cast<uint32_t*>(&h); }
__device__ __forceinline__ uint32_t ex2h2(uint32_t x) {
    uint32_t r;
    asm("ex2.approx.f16x2 %0, %1;" : "=r"(r) : "r"(x));
    return r;
}
__device__ __forceinline__ void mma16(float* d, uint32_t a0, uint32_t a1, uint32_t a2, uint32_t a3,
                                      uint32_t b0, uint32_t b1) {
    asm volatile(
        "mma.sync.aligned.m16n8k16.row.col.f32.f16.f16.f32 "
        "{%0,%1,%2,%3},{%4,%5,%6,%7},{%8,%9},{%0,%1,%2,%3};"
        : "+f"(d[0]), "+f"(d[1]), "+f"(d[2]), "+f"(d[3])
        : "r"(a0), "r"(a1), "r"(a2), "r"(a3), "r"(b0), "r"(b1));
}
__device__ __forceinline__ void ldm4(uint32_t* r, uint32_t a) {
    asm volatile("ldmatrix.sync.aligned.m8n8.x4.shared.b16 {%0,%1,%2,%3}, [%4];"
        : "=r"(r[0]), "=r"(r[1]), "=r"(r[2]), "=r"(r[3]) : "r"(a));
}
__device__ __forceinline__ void ldm4t(uint32_t* r, uint32_t a) {
    asm volatile("ldmatrix.sync.aligned.m8n8.x4.trans.shared.b16 {%0,%1,%2,%3}, [%4];"
        : "=r"(r[0]), "=r"(r[1]), "=r"(r[2]), "=r"(r[3]) : "r"(a));
}

// ---------------------------------------------------------------------------
// fp32 -> fp16 conversion
// ---------------------------------------------------------------------------
__global__ void __launch_bounds__(256) convert_kernel(
    const float* __restrict__ q, const float* __restrict__ k, const float* __restrict__ v,
    const float* __restrict__ Wq, const float* __restrict__ Wk,
    const float* __restrict__ Wv, const float* __restrict__ Wo)
{
    const float* src; __half* dst; int n;
    switch (blockIdx.y) {
        case 0: src = q;  dst = c_q;  n = BB * SS * DD; break;
        case 1: src = k;  dst = c_k;  n = BB * SS * DD; break;
        case 2: src = v;  dst = c_v;  n = BB * SS * DD; break;
        case 3: src = Wq; dst = c_wq; n = DD * DD; break;
        case 4: src = Wk; dst = c_wk; n = DD * DD; break;
        case 5: src = Wv; dst = c_wv; n = DD * DD; break;
        default: src = Wo; dst = c_wo; n = DD * DD; break;
    }
    const int n4 = n >> 2;
    for (int i = blockIdx.x * 256 + threadIdx.x; i < n4; i += gridDim.x * 256) {
        float4 f = reinterpret_cast<const float4*>(src)[i];
        reinterpret_cast<__half2*>(dst)[2 * i]     = __floats2half2_rn(f.x, f.y);
        reinterpret_cast<__half2*>(dst)[2 * i + 1] = __floats2half2_rn(f.z, f.w);
    }
}

// ---------------------------------------------------------------------------
// fp16 GEMM: 128x128 CTA tile, BK=64, 128 threads (4 warps, warp tile 64x64),
// 3-stage cp.async ring, 2 CTAs/SM.
// ---------------------------------------------------------------------------
#define PALD 72       // A row pitch (halves) = 144B
#define PBLD 136      // B row pitch (halves) = 272B
#define A_STG 18432   // 128 * 144
#define B_STG 17408   // 64 * 272
#define B_BASE (3 * A_STG)                     // 55296
#define PROJ_SMEM_BYTES (B_BASE + 3 * B_STG)   // 107520

using AF = wmma::fragment<wmma::matrix_a, 16, 16, 16, __half, wmma::row_major>;
using BF = wmma::fragment<wmma::matrix_b, 16, 16, 16, __half, wmma::row_major>;
using CF = wmma::fragment<wmma::accumulator, 16, 16, 16, float>;

__device__ __forceinline__ void gemm_fp16(const __half* __restrict__ A,
                                          const __half* __restrict__ Wm,
                                          const float* __restrict__ bias,
                                          void* __restrict__ outp, int half_head)
{
    extern __shared__ char dsm[];
    const uint32_t sb = smem_u32(dsm);
    const int tid  = threadIdx.x;
    const int warp = tid >> 5;
    const int lid  = tid & 31;
    const int wm   = warp >> 1;
    const int wn   = warp & 1;
    const int n0   = blockIdx.x * 128;
    const int m0   = blockIdx.y * 128;

    CF acc[4][4];
#pragma unroll
    for (int mf = 0; mf < 4; mf++)
#pragma unroll
        for (int nf = 0; nf < 4; nf++) wmma::fill_fragment(acc[mf][nf], 0.0f);

    auto issue = [&](int it) {
        const int kt = it * 64, stg = it % 3;
        const uint32_t ad = sb + stg * A_STG;
        const uint32_t bd = sb + B_BASE + stg * B_STG;
#pragma unroll
        for (int t = 0; t < 8; t++) {
            int id = tid + t * 128;                 // A: 128 rows x 8 x 16B
            cp16(ad + (id >> 3) * 144 + (id & 7) * 16,
                 A + (size_t)(m0 + (id >> 3)) * DD + kt + (id & 7) * 8);
        }
#pragma unroll
        for (int t = 0; t < 8; t++) {
            int id = tid + t * 128;                 // B: 64 rows x 16 x 16B
            cp16(bd + (id >> 4) * 272 + (id & 15) * 16,
                 Wm + (size_t)(kt + (id >> 4)) * DD + n0 + (id & 15) * 8);
        }
        asm volatile("cp.async.commit_group;" ::: "memory");
    };

    issue(0);
    issue(1);
    for (int it = 0; it < 16; it++) {
        if (it < 15) asm volatile("cp.async.wait_group 1;" ::: "memory");
        else         asm volatile("cp.async.wait_group 0;" ::: "memory");
        __syncthreads();
        if (it + 2 < 16) issue(it + 2);

        const int stg = it % 3;
        const __half* Ab = reinterpret_cast<const __half*>(dsm) + stg * (A_STG / 2);
        const __half* Bb = reinterpret_cast<const __half*>(dsm + B_BASE) + stg * (B_STG / 2);
        AF a[4]; BF b;
#pragma unroll
        for (int kk = 0; kk < 64; kk += 16) {
#pragma unroll
            for (int mf = 0; mf < 4; mf++)
                wmma::load_matrix_sync(a[mf], Ab + (wm * 64 + mf * 16) * PALD + kk, PALD);
#pragma unroll
            for (int nf = 0; nf < 4; nf++) {
                wmma::load_matrix_sync(b, Bb + kk * PBLD + wn * 64 + nf * 16, PBLD);
#pragma unroll
                for (int mf = 0; mf < 4; mf++)
                    wmma::mma_sync(acc[mf][nf], a[mf], b, acc[mf][nf]);
            }
        }
    }
    __syncthreads();

    // Epilogue: per-warp smem scratch (aliases ring)
    float* eps = reinterpret_cast<float*>(dsm) + warp * 640;   // 32 x 20 floats
#pragma unroll
    for (int nf = 0; nf < 4; nf++) {
#pragma unroll
        for (int mfp = 0; mfp < 2; mfp++) {
            wmma::store_matrix_sync(eps,            acc[2 * mfp][nf],     20, wmma::mem_row_major);
            wmma::store_matrix_sync(eps + 16 * 20,  acc[2 * mfp + 1][nf], 20, wmma::mem_row_major);
            __syncwarp();
            const int m   = m0 + wm * 64 + mfp * 32 + lid;
            const int nc0 = n0 + wn * 64 + nf * 16;
            if (half_head) {
                const int hh = nc0 >> 6, d = nc0 & 63;
                __half* dst = (__half*)outp +
                    ((size_t)((m >> 11) * HH + hh) * SS + (m & 2047)) * DH + d;
#pragma unroll
                for (int c = 0; c < 16; c += 2) {
                    float x = eps[lid * 20 + c]     + bias[nc0 + c];
                    float y = eps[lid * 20 + c + 1] + bias[nc0 + c + 1];
                    *reinterpret_cast<__half2*>(dst + c) = __floats2half2_rn(x, y);
                }
            } else {
                float* dst = (float*)outp + (size_t)m * DD + nc0;
#pragma unroll
                for (int c = 0; c < 16; c++) dst[c] = eps[lid * 20 + c] + bias[nc0 + c];
            }
            __syncwarp();
        }
    }
}

__global__ void __launch_bounds__(128, 2) proj_qkv_kernel(
    const float* __restrict__ bq, const float* __restrict__ bk, const float* __restrict__ bv)
{
    const int z = blockIdx.z;
    const __half* A    = (z == 0) ? c_q  : (z == 1) ? c_k  : c_v;
    const __half* W    = (z == 0) ? c_wq : (z == 1) ? c_wk : c_wv;
    const float* bias  = (z == 0) ? bq   : (z == 1) ? bk   : bv;
    __half* out        = (z == 0) ? hq   : (z == 1) ? hk   : hv;
    gemm_fp16(A, W, bias, out, 1);
}

__global__ void __launch_bounds__(128, 2) proj_out_kernel(
    const float* __restrict__ bo, float* __restrict__ out)
{
    gemm_fp16(hctx, c_wo, bo, out, 0);
}

// ---------------------------------------------------------------------------
// Flash attention: fp16 mma + ldmatrix, 2-stage cp.async K/V ring,
// softmax via ex2.approx.f16x2 (P lands directly in fp16 A-fragment layout).
// ---------------------------------------------------------------------------
#define KLD 72
#define VLD 72
#define KBUF (64 * KLD)           // halves per buffer
#define KBUF_B (KBUF * 2)         // bytes between buffers

__global__ void __launch_bounds__(256, 2) attn_kernel(const float* __restrict__ mask)
{
    __shared__ __half Ks[2][KBUF];
    __shared__ __half Vs[2][KBUF];
    __shared__ float maskB[2][64];

    const int tid  = threadIdx.x;
    const int warp = tid >> 5;
    const int lane = tid & 31;
    const int g    = lane >> 2;
    const int t4   = lane & 3;
    const int wr0  = warp * 16;
    const int bh   = blockIdx.x;
    const int qt   = blockIdx.y;
    const int bb   = bh >> 4;
    const int hi   = bh & 15;

    const __half* Qg = hq + ((size_t)bh * SS + qt * 128 + wr0) * DH;
    const __half* Kg = hk + (size_t)bh * SS * DH;
    const __half* Vg = hv + (size_t)bh * SS * DH;
    const float*  Mg = mask + (size_t)bb * SS;

    // Q fragments, pre-scaled by 1/sqrt(DH)=0.125 (exact in fp16)
    const __half2 qsc = __half2half2(__float2half_rn(0.125f));
    uint32_t Qa[4][4];
#pragma unroll
    for (int kc = 0; kc < 4; kc++) {
        __half2 v0 = *reinterpret_cast<const __half2*>(Qg + (size_t)g * DH + kc * 16 + 2 * t4);
        __half2 v1 = *reinterpret_cast<const __half2*>(Qg + (size_t)(g + 8) * DH + kc * 16 + 2 * t4);
        __half2 v2 = *reinterpret_cast<const __half2*>(Qg + (size_t)g * DH + kc * 16 + 2 * t4 + 8);
        __half2 v3 = *reinterpret_cast<const __half2*>(Qg + (size_t)(g + 8) * DH + kc * 16 + 2 * t4 + 8);
        Qa[kc][0] = h2u(__hmul2(v0, qsc));
        Qa[kc][1] = h2u(__hmul2(v1, qsc));
        Qa[kc][2] = h2u(__hmul2(v2, qsc));
        Qa[kc][3] = h2u(__hmul2(v3, qsc));
    }

    // ldmatrix lane bases (buffer 0; add buf*KBUF_B for buffer 1)
    const int krow = (lane & 7) + ((lane >> 4) & 1) * 8;
    const int kcol = ((lane >> 3) & 1) * 8;
    uint32_t kaddr[4];
#pragma unroll
    for (int jp = 0; jp < 4; jp++)
        kaddr[jp] = smem_u32(&Ks[0][(16 * jp + krow) * KLD + kcol]);
    const int vrow = (lane & 7) + ((lane >> 3) & 1) * 8;
    const int vcol = ((lane >> 4) & 1) * 8;
    uint32_t vaddr[4];
#pragma unroll
    for (int dp = 0; dp < 4; dp++)
        vaddr[dp] = smem_u32(&Vs[0][vrow * VLD + 16 * dp + vcol]);

    auto prefetch = [&](int ti) {
        const int kt0 = ti * 64, buf = ti & 1;
#pragma unroll
        for (int t = 0; t < 2; t++) {
            int idx = tid + t * 256;
            int r = idx >> 3, c = (idx & 7) * 8;
            cp16(smem_u32(&Ks[buf][r * KLD + c]), Kg + (size_t)(kt0 + r) * DH + c);
            cp16(smem_u32(&Vs[buf][r * VLD + c]), Vg + (size_t)(kt0 + r) * DH + c);
        }
        if (tid < 16) cp16(smem_u32(&maskB[buf][tid * 4]), Mg + kt0 + tid * 4);
        asm volatile("cp.async.commit_group;" ::: "memory");
    };

    float O[8][4];
#pragma unroll
    for (int d = 0; d < 8; d++) { O[d][0] = O[d][1] = O[d][2] = O[d][3] = 0.f; }
    float m0 = -1e30f, m1 = -1e30f, l0 = 0.f, l1 = 0.f;
    const float L2E = 1.44269504f;

    prefetch(0);
    for (int ti = 0; ti < 32; ti++) {
        asm volatile("cp.async.wait_group 0;" ::: "memory");
        __syncthreads();
        if (ti + 1 < 32) prefetch(ti + 1);   // flies during compute

        const int buf = ti & 1;
        const uint32_t kofs = buf * KBUF_B;

        // S = Q K^T (Q pre-scaled)
        float S[8][4];
#pragma unroll
        for (int j = 0; j < 8; j++) { S[j][0] = S[j][1] = S[j][2] = S[j][3] = 0.f; }
#pragma unroll
        for (int kc = 0; kc < 4; kc++) {
#pragma unroll
            for (int jp = 0; jp < 4; jp++) {
                uint32_t br[4];
                ldm4(br, kaddr[jp] + kofs + kc * 32);
                mma16(S[2 * jp],     Qa[kc][0], Qa[kc][1], Qa[kc][2], Qa[kc][3], br[0], br[1]);
                mma16(S[2 * jp + 1], Qa[kc][0], Qa[kc][1], Qa[kc][2], Qa[kc][3], br[2], br[3]);
            }
        }

        // masked max
        float mx0 = -1e30f, mx1 = -1e30f;
#pragma unroll
        for (int j = 0; j < 8; j++) {
            float k0 = maskB[buf][8 * j + 2 * t4]     * -1e9f;
            float k1 = maskB[buf][8 * j + 2 * t4 + 1] * -1e9f;
            S[j][0] += k0; S[j][1] += k1; S[j][2] += k0; S[j][3] += k1;
            mx0 = fmaxf(mx0, fmaxf(S[j][0], S[j][1]));
            mx1 = fmaxf(mx1, fmaxf(S[j][2], S[j][3]));
        }
        mx0 = fmaxf(mx0, __shfl_xor_sync(0xffffffffu, mx0, 1));
        mx0 = fmaxf(mx0, __shfl_xor_sync(0xffffffffu, mx0, 2));
        mx1 = fmaxf(mx1, __shfl_xor_sync(0xffffffffu, mx1, 1));
        mx1 = fmaxf(mx1, __shfl_xor_sync(0xffffffffu, mx1, 2));
        const float nm0 = fmaxf(m0, mx0);
        const float nm1 = fmaxf(m1, mx1);
        const float al0 = __expf(m0 - nm0);
        const float al1 = __expf(m1 - nm1);
        m0 = nm0; m1 = nm1;

        // P = exp(S - nm) via ex2.f16x2 -> directly in fp16 A-fragment layout
        uint32_t P[8][2];
        const float b0 = -nm0 * L2E, b1 = -nm1 * L2E;
        float s0 = 0.f, s1 = 0.f;
#pragma unroll
        for (int j = 0; j < 8; j++) {
            float t0 = fmaf(S[j][0], L2E, b0);
            float t1 = fmaf(S[j][1], L2E, b0);
            float t2 = fmaf(S[j][2], L2E, b1);
            float t3 = fmaf(S[j][3], L2E, b1);
            uint32_t p0 = ex2h2(h2u(__floats2half2_rn(t0, t1)));
            uint32_t p1 = ex2h2(h2u(__floats2half2_rn(t2, t3)));
            P[j][0] = p0; P[j][1] = p1;
            float2 f0 = __half22float2(*reinterpret_cast<__half2*>(&p0));
            float2 f1 = __half22float2(*reinterpret_cast<__half2*>(&p1));
            s0 += f0.x + f0.y;
            s1 += f1.x + f1.y;
        }
        s0 += __shfl_xor_sync(0xffffffffu, s0, 1);
        s0 += __shfl_xor_sync(0xffffffffu, s0, 2);
        s1 += __shfl_xor_sync(0xffffffffu, s1, 1);
        s1 += __shfl_xor_sync(0xffffffffu, s1, 2);
        l0 = l0 * al0 + s0;
        l1 = l1 * al1 + s1;
#pragma unroll
        for (int d = 0; d < 8; d++) {
            O[d][0] *= al0; O[d][1] *= al0;
            O[d][2] *= al1; O[d][3] *= al1;
        }

        // O += P V
#pragma unroll
        for (int kj = 0; kj < 4; kj++) {
            uint32_t a0 = P[2 * kj][0];
            uint32_t a1 = P[2 * kj][1];
            uint32_t a2 = P[2 * kj + 1][0];
            uint32_t a3 = P[2 * kj + 1][1];
#pragma unroll
            for (int dp = 0; dp < 4; dp++) {
                uint32_t br[4];
                ldm4t(br, vaddr[dp] + kofs + kj * (16 * VLD * 2));
                mma16(O[2 * dp],     a0, a1, a2, a3, br[0], br[1]);
                mma16(O[2 * dp + 1], a0, a1, a2, a3, br[2], br[3]);
            }
        }
    }

    const float inv0 = 1.0f / l0;
    const float inv1 = 1.0f / l1;
    __half* base = hctx + ((size_t)(bb * SS + qt * 128 + wr0)) * DD + hi * DH;
#pragma unroll
    for (int d = 0; d < 8; d++) {
        *reinterpret_cast<__half2*>(base + (size_t)g * DD + 8 * d + 2 * t4) =
            __floats2half2_rn(O[d][0] * inv0, O[d][1] * inv0);
        *reinterpret_cast<__half2*>(base + (size_t)(g + 8) * DD + 8 * d + 2 * t4) =
            __floats2half2_rn(O[d][2] * inv1, O[d][3] * inv1);
    }
}

// ---------------------------------------------------------------------------
extern "C" void kernel_launch(void* const* d_in, const int* in_sizes, int n_in,
                              void* d_out, int out_size)
{
    const float* query = (const float*)d_in[0];
    const float* key   = (const float*)d_in[1];
    const float* value = (const float*)d_in[2];
    const float* mask  = (const float*)d_in[3];
    const float* Wq    = (const float*)d_in[4];
    const float* bq    = (const float*)d_in[5];
    const float* Wk    = (const float*)d_in[6];
    const float* bk    = (const float*)d_in[7];
    const float* Wv    = (const float*)d_in[8];
    const float* bv    = (const float*)d_in[9];
    const float* Wo    = (const float*)d_in[10];
    const float* bo    = (const float*)d_in[11];
    float* out = (float*)d_out;

    static int configured = 0;
    if (!configured) {
        cudaFuncSetAttribute(proj_qkv_kernel, cudaFuncAttributeMaxDynamicSharedMemorySize, PROJ_SMEM_BYTES);
        cudaFuncSetAttribute(proj_out_kernel, cudaFuncAttributeMaxDynamicSharedMemorySize, PROJ_SMEM_BYTES);
        configured = 1;
    }

    convert_kernel<<<dim3(512, 7), 256>>>(query, key, value, Wq, Wk, Wv, Wo);
    proj_qkv_kernel<<<dim3(8, 32, 3), 128, PROJ_SMEM_BYTES>>>(bq, bk, bv);
    attn_kernel<<<dim3(32, 16), 256>>>(mask);
    proj_out_kernel<<<dim3(8, 32), 128, PROJ_SMEM_BYTES>>>(bo, out);
}

// round 10
// speedup vs baseline: 5.9973x; 1.1445x over previous
#include <cuda_runtime.h>
#include <cuda_fp16.h>
#include <cstdint>

#define BB 2
#define SS 2048
#define DD 1024
#define HH 16
#define DH 64

// ---- scratch (__device__ globals; no allocations allowed) ----
__device__ __half c_q[BB * SS * DD], c_k[BB * SS * DD], c_v[BB * SS * DD];
__device__ __half c_wq[DD * DD], c_wk[DD * DD], c_wv[DD * DD], c_wo[DD * DD];
__device__ __half hq[BB * HH * SS * DH], hk[BB * HH * SS * DH], hv[BB * HH * SS * DH];
__device__ __half hctx[BB * SS * DD];

// ---------------- helpers ----------------
__device__ __forceinline__ uint32_t smem_u32(const void* p) {
    uint32_t a;
    asm("{ .reg .u64 t; cvta.to.shared.u64 t, %1; cvt.u32.u64 %0, t; }" : "=r"(a) : "l"(p));
    return a;
}
__device__ __forceinline__ void cp16(uint32_t d, const void* s) {
    asm volatile("cp.async.cg.shared.global [%0], [%1], 16;" :: "r"(d), "l"(s) : "memory");
}
__device__ __forceinline__ uint32_t h2u(__half2 h) { return *reinterpret_cast<uint32_t*>(&h); }
__device__ __forceinline__ uint32_t ex2h2(uint32_t x) {
    uint32_t r;
    asm("ex2.approx.f16x2 %0, %1;" : "=r"(r) : "r"(x));
    return r;
}
__device__ __forceinline__ void mma16(float* d, uint32_t a0, uint32_t a1, uint32_t a2, uint32_t a3,
                                      uint32_t b0, uint32_t b1) {
    asm volatile(
        "mma.sync.aligned.m16n8k16.row.col.f32.f16.f16.f32 "
        "{%0,%1,%2,%3},{%4,%5,%6,%7},{%8,%9},{%0,%1,%2,%3};"
        : "+f"(d[0]), "+f"(d[1]), "+f"(d[2]), "+f"(d[3])
        : "r"(a0), "r"(a1), "r"(a2), "r"(a3), "r"(b0), "r"(b1));
}
__device__ __forceinline__ void ldm4(uint32_t* r, uint32_t a) {
    asm volatile("ldmatrix.sync.aligned.m8n8.x4.shared.b16 {%0,%1,%2,%3}, [%4];"
        : "=r"(r[0]), "=r"(r[1]), "=r"(r[2]), "=r"(r[3]) : "r"(a));
}
__device__ __forceinline__ void ldm4t(uint32_t* r, uint32_t a) {
    asm volatile("ldmatrix.sync.aligned.m8n8.x4.trans.shared.b16 {%0,%1,%2,%3}, [%4];"
        : "=r"(r[0]), "=r"(r[1]), "=r"(r[2]), "=r"(r[3]) : "r"(a));
}

// ---------------------------------------------------------------------------
// fp32 -> fp16 conversion
// ---------------------------------------------------------------------------
__global__ void __launch_bounds__(256) convert_kernel(
    const float* __restrict__ q, const float* __restrict__ k, const float* __restrict__ v,
    const float* __restrict__ Wq, const float* __restrict__ Wk,
    const float* __restrict__ Wv, const float* __restrict__ Wo)
{
    const float* src; __half* dst; int n;
    switch (blockIdx.y) {
        case 0: src = q;  dst = c_q;  n = BB * SS * DD; break;
        case 1: src = k;  dst = c_k;  n = BB * SS * DD; break;
        case 2: src = v;  dst = c_v;  n = BB * SS * DD; break;
        case 3: src = Wq; dst = c_wq; n = DD * DD; break;
        case 4: src = Wk; dst = c_wk; n = DD * DD; break;
        case 5: src = Wv; dst = c_wv; n = DD * DD; break;
        default: src = Wo; dst = c_wo; n = DD * DD; break;
    }
    const int n4 = n >> 2;
    for (int i = blockIdx.x * 256 + threadIdx.x; i < n4; i += gridDim.x * 256) {
        float4 f = reinterpret_cast<const float4*>(src)[i];
        reinterpret_cast<__half2*>(dst)[2 * i]     = __floats2half2_rn(f.x, f.y);
        reinterpret_cast<__half2*>(dst)[2 * i + 1] = __floats2half2_rn(f.z, f.w);
    }
}

// ---------------------------------------------------------------------------
// fp16 GEMM, raw mma + ldmatrix: 128x128 CTA tile, BK=32, 256 threads
// (8 warps, 4Mx2N, warp tile 32x64), 3-stage cp.async ring, 2 CTAs/SM.
// A row-major [m][k] (non-trans ldmatrix), W K-major [k][n] (trans ldmatrix).
// ---------------------------------------------------------------------------
#define A_PITCH 80      // bytes per A smem row (32 halves + 8 pad)
#define B_PITCH 272     // bytes per B smem row (128 halves + 8 pad)
#define A_STG 10240     // 128 * 80
#define B_STG 8704      // 32 * 272
#define B_BASE (3 * A_STG)                     // 30720
#define PROJ_SMEM_BYTES (B_BASE + 3 * B_STG)   // 56832

__device__ __forceinline__ void gemm_fp16(const __half* __restrict__ A,
                                          const __half* __restrict__ Wm,
                                          const float* __restrict__ bias,
                                          void* __restrict__ outp, int half_head)
{
    extern __shared__ char dsm[];
    const uint32_t sb = smem_u32(dsm);
    const int tid  = threadIdx.x;
    const int warp = tid >> 5;
    const int lane = tid & 31;
    const int g    = lane >> 2;
    const int t4   = lane & 3;
    const int wm   = warp >> 1;    // 0..3 (32-row strip)
    const int wn   = warp & 1;     // 0..1 (64-col strip)
    const int n0   = blockIdx.x * 128;
    const int m0   = blockIdx.y * 128;

    float acc[2][8][4];
#pragma unroll
    for (int mf = 0; mf < 2; mf++)
#pragma unroll
        for (int nf = 0; nf < 8; nf++)
#pragma unroll
            for (int i = 0; i < 4; i++) acc[mf][nf][i] = 0.f;

    // ldmatrix lane base addresses (stage 0)
    // A (non-trans, m16k16): lanes 0-15 -> row lane, col 0; 16-31 -> row lane, col 8
    const int arow = lane & 15;
    const int acol = (lane >> 4) * 16;   // bytes (8 halves)
    uint32_t aaddr[2];
#pragma unroll
    for (int mf = 0; mf < 2; mf++)
        aaddr[mf] = sb + (wm * 32 + mf * 16 + arow) * A_PITCH + acol;
    // B (trans, k16 x n16 tile from row-major [k][n]):
    const int brow = (lane & 7) + ((lane >> 3) & 1) * 8;
    const int bcol = ((lane >> 4) & 1) * 16;  // bytes
    uint32_t baddr[4];
#pragma unroll
    for (int nfp = 0; nfp < 4; nfp++)
        baddr[nfp] = sb + B_BASE + brow * B_PITCH + (wn * 64 + nfp * 16) * 2 + bcol;

    auto issue = [&](int it) {
        const int kt = it * 32, stg = it % 3;
        const uint32_t ad = sb + stg * A_STG;
        const uint32_t bd = sb + B_BASE + stg * B_STG;
#pragma unroll
        for (int t = 0; t < 2; t++) {
            int id = tid + t * 256;                 // A: 128 rows x 4 x 16B
            cp16(ad + (id >> 2) * A_PITCH + (id & 3) * 16,
                 A + (size_t)(m0 + (id >> 2)) * DD + kt + (id & 3) * 8);
        }
#pragma unroll
        for (int t = 0; t < 2; t++) {
            int id = tid + t * 256;                 // B: 32 rows x 16 x 16B
            cp16(bd + (id >> 4) * B_PITCH + (id & 15) * 16,
                 Wm + (size_t)(kt + (id >> 4)) * DD + n0 + (id & 15) * 8);
        }
        asm volatile("cp.async.commit_group;" ::: "memory");
    };

    issue(0);
    issue(1);
    for (int it = 0; it < 32; it++) {
        if (it < 31) asm volatile("cp.async.wait_group 1;" ::: "memory");
        else         asm volatile("cp.async.wait_group 0;" ::: "memory");
        __syncthreads();
        if (it + 2 < 32) issue(it + 2);

        const int stg = it % 3;
        const uint32_t aofs = stg * A_STG;
        const uint32_t bofs = stg * B_STG;
#pragma unroll
        for (int kk = 0; kk < 2; kk++) {
            uint32_t aa[2][4];
            ldm4(aa[0], aaddr[0] + aofs + kk * 32);
            ldm4(aa[1], aaddr[1] + aofs + kk * 32);
#pragma unroll
            for (int nfp = 0; nfp < 4; nfp++) {
                uint32_t br[4];
                ldm4t(br, baddr[nfp] + bofs + kk * (16 * B_PITCH));
                mma16(acc[0][2 * nfp],     aa[0][0], aa[0][1], aa[0][2], aa[0][3], br[0], br[1]);
                mma16(acc[0][2 * nfp + 1], aa[0][0], aa[0][1], aa[0][2], aa[0][3], br[2], br[3]);
                mma16(acc[1][2 * nfp],     aa[1][0], aa[1][1], aa[1][2], aa[1][3], br[0], br[1]);
                mma16(acc[1][2 * nfp + 1], aa[1][0], aa[1][1], aa[1][2], aa[1][3], br[2], br[3]);
            }
        }
        __syncthreads();
    }

    // Epilogue: bias-add in regs, direct stores (no smem round trip).
    // acc[mf][nf] -> rows m0+wm*32+mf*16+{g,g+8}, cols n0+wn*64+nf*8+2*t4 (+1)
    const int ncb = n0 + wn * 64;
    if (half_head) {
        const int hh = ncb >> 6;               // 64-col warp strip = one head
        __half* outh = (__half*)outp;
#pragma unroll
        for (int mf = 0; mf < 2; mf++) {
            const int r0 = m0 + wm * 32 + mf * 16 + g;
            const int s0 = r0 & 2047, b0i = r0 >> 11;
            __half* d0 = outh + ((size_t)(b0i * HH + hh) * SS + s0) * DH;
            __half* d1 = outh + ((size_t)(((r0 + 8) >> 11) * HH + hh) * SS + ((r0 + 8) & 2047)) * DH;
#pragma unroll
            for (int nf = 0; nf < 8; nf++) {
                const int c = ncb + nf * 8 + 2 * t4;
                const float bx = bias[c], by = bias[c + 1];
                const int d = nf * 8 + 2 * t4;
                *reinterpret_cast<__half2*>(d0 + d) =
                    __floats2half2_rn(acc[mf][nf][0] + bx, acc[mf][nf][1] + by);
                *reinterpret_cast<__half2*>(d1 + d) =
                    __floats2half2_rn(acc[mf][nf][2] + bx, acc[mf][nf][3] + by);
            }
        }
    } else {
        float* outf = (float*)outp;
#pragma unroll
        for (int mf = 0; mf < 2; mf++) {
            const int r0 = m0 + wm * 32 + mf * 16 + g;
            float* d0 = outf + (size_t)r0 * DD;
            float* d1 = outf + (size_t)(r0 + 8) * DD;
#pragma unroll
            for (int nf = 0; nf < 8; nf++) {
                const int c = ncb + nf * 8 + 2 * t4;
                const float bx = bias[c], by = bias[c + 1];
                float2 v0 = make_float2(acc[mf][nf][0] + bx, acc[mf][nf][1] + by);
                float2 v1 = make_float2(acc[mf][nf][2] + bx, acc[mf][nf][3] + by);
                *reinterpret_cast<float2*>(d0 + c) = v0;
                *reinterpret_cast<float2*>(d1 + c) = v1;
            }
        }
    }
}

__global__ void __launch_bounds__(256, 2) proj_qkv_kernel(
    const float* __restrict__ bq, const float* __restrict__ bk, const float* __restrict__ bv)
{
    const int z = blockIdx.z;
    const __half* A    = (z == 0) ? c_q  : (z == 1) ? c_k  : c_v;
    const __half* W    = (z == 0) ? c_wq : (z == 1) ? c_wk : c_wv;
    const float* bias  = (z == 0) ? bq   : (z == 1) ? bk   : bv;
    __half* out        = (z == 0) ? hq   : (z == 1) ? hk   : hv;
    gemm_fp16(A, W, bias, out, 1);
}

__global__ void __launch_bounds__(256, 2) proj_out_kernel(
    const float* __restrict__ bo, float* __restrict__ out)
{
    gemm_fp16(hctx, c_wo, bo, out, 0);
}

// ---------------------------------------------------------------------------
// Flash attention (unchanged from R9): fp16 mma + ldmatrix, 2-stage cp.async
// ring, softmax via ex2.approx.f16x2.
// ---------------------------------------------------------------------------
#define KLD 72
#define VLD 72
#define KBUF (64 * KLD)
#define KBUF_B (KBUF * 2)

__global__ void __launch_bounds__(256, 2) attn_kernel(const float* __restrict__ mask)
{
    __shared__ __half Ks[2][KBUF];
    __shared__ __half Vs[2][KBUF];
    __shared__ float maskB[2][64];

    const int tid  = threadIdx.x;
    const int warp = tid >> 5;
    const int lane = tid & 31;
    const int g    = lane >> 2;
    const int t4   = lane & 3;
    const int wr0  = warp * 16;
    const int bh   = blockIdx.x;
    const int qt   = blockIdx.y;
    const int bb   = bh >> 4;
    const int hi   = bh & 15;

    const __half* Qg = hq + ((size_t)bh * SS + qt * 128 + wr0) * DH;
    const __half* Kg = hk + (size_t)bh * SS * DH;
    const __half* Vg = hv + (size_t)bh * SS * DH;
    const float*  Mg = mask + (size_t)bb * SS;

    const __half2 qsc = __half2half2(__float2half_rn(0.125f));
    uint32_t Qa[4][4];
#pragma unroll
    for (int kc = 0; kc < 4; kc++) {
        __half2 v0 = *reinterpret_cast<const __half2*>(Qg + (size_t)g * DH + kc * 16 + 2 * t4);
        __half2 v1 = *reinterpret_cast<const __half2*>(Qg + (size_t)(g + 8) * DH + kc * 16 + 2 * t4);
        __half2 v2 = *reinterpret_cast<const __half2*>(Qg + (size_t)g * DH + kc * 16 + 2 * t4 + 8);
        __half2 v3 = *reinterpret_cast<const __half2*>(Qg + (size_t)(g + 8) * DH + kc * 16 + 2 * t4 + 8);
        Qa[kc][0] = h2u(__hmul2(v0, qsc));
        Qa[kc][1] = h2u(__hmul2(v1, qsc));
        Qa[kc][2] = h2u(__hmul2(v2, qsc));
        Qa[kc][3] = h2u(__hmul2(v3, qsc));
    }

    const int krow = (lane & 7) + ((lane >> 4) & 1) * 8;
    const int kcol = ((lane >> 3) & 1) * 8;
    uint32_t kaddr[4];
#pragma unroll
    for (int jp = 0; jp < 4; jp++)
        kaddr[jp] = smem_u32(&Ks[0][(16 * jp + krow) * KLD + kcol]);
    const int vrow = (lane & 7) + ((lane >> 3) & 1) * 8;
    const int vcol = ((lane >> 4) & 1) * 8;
    uint32_t vaddr[4];
#pragma unroll
    for (int dp = 0; dp < 4; dp++)
        vaddr[dp] = smem_u32(&Vs[0][vrow * VLD + 16 * dp + vcol]);

    auto prefetch = [&](int ti) {
        const int kt0 = ti * 64, buf = ti & 1;
#pragma unroll
        for (int t = 0; t < 2; t++) {
            int idx = tid + t * 256;
            int r = idx >> 3, c = (idx & 7) * 8;
            cp16(smem_u32(&Ks[buf][r * KLD + c]), Kg + (size_t)(kt0 + r) * DH + c);
            cp16(smem_u32(&Vs[buf][r * VLD + c]), Vg + (size_t)(kt0 + r) * DH + c);
        }
        if (tid < 16) cp16(smem_u32(&maskB[buf][tid * 4]), Mg + kt0 + tid * 4);
        asm volatile("cp.async.commit_group;" ::: "memory");
    };

    float O[8][4];
#pragma unroll
    for (int d = 0; d < 8; d++) { O[d][0] = O[d][1] = O[d][2] = O[d][3] = 0.f; }
    float m0 = -1e30f, m1 = -1e30f, l0 = 0.f, l1 = 0.f;
    const float L2E = 1.44269504f;

    prefetch(0);
    for (int ti = 0; ti < 32; ti++) {
        asm volatile("cp.async.wait_group 0;" ::: "memory");
        __syncthreads();
        if (ti + 1 < 32) prefetch(ti + 1);

        const int buf = ti & 1;
        const uint32_t kofs = buf * KBUF_B;

        float S[8][4];
#pragma unroll
        for (int j = 0; j < 8; j++) { S[j][0] = S[j][1] = S[j][2] = S[j][3] = 0.f; }
#pragma unroll
        for (int kc = 0; kc < 4; kc++) {
#pragma unroll
            for (int jp = 0; jp < 4; jp++) {
                uint32_t br[4];
                ldm4(br, kaddr[jp] + kofs + kc * 32);
                mma16(S[2 * jp],     Qa[kc][0], Qa[kc][1], Qa[kc][2], Qa[kc][3], br[0], br[1]);
                mma16(S[2 * jp + 1], Qa[kc][0], Qa[kc][1], Qa[kc][2], Qa[kc][3], br[2], br[3]);
            }
        }

        float mx0 = -1e30f, mx1 = -1e30f;
#pragma unroll
        for (int j = 0; j < 8; j++) {
            float k0 = maskB[buf][8 * j + 2 * t4]     * -1e9f;
            float k1 = maskB[buf][8 * j + 2 * t4 + 1] * -1e9f;
            S[j][0] += k0; S[j][1] += k1; S[j][2] += k0; S[j][3] += k1;
            mx0 = fmaxf(mx0, fmaxf(S[j][0], S[j][1]));
            mx1 = fmaxf(mx1, fmaxf(S[j][2], S[j][3]));
        }
        mx0 = fmaxf(mx0, __shfl_xor_sync(0xffffffffu, mx0, 1));
        mx0 = fmaxf(mx0, __shfl_xor_sync(0xffffffffu, mx0, 2));
        mx1 = fmaxf(mx1, __shfl_xor_sync(0xffffffffu, mx1, 1));
        mx1 = fmaxf(mx1, __shfl_xor_sync(0xffffffffu, mx1, 2));
        const float nm0 = fmaxf(m0, mx0);
        const float nm1 = fmaxf(m1, mx1);
        const float al0 = __expf(m0 - nm0);
        const float al1 = __expf(m1 - nm1);
        m0 = nm0; m1 = nm1;

        uint32_t P[8][2];
        const float b0 = -nm0 * L2E, b1 = -nm1 * L2E;
        float s0 = 0.f, s1 = 0.f;
#pragma unroll
        for (int j = 0; j < 8; j++) {
            float t0 = fmaf(S[j][0], L2E, b0);
            float t1 = fmaf(S[j][1], L2E, b0);
            float t2 = fmaf(S[j][2], L2E, b1);
            float t3 = fmaf(S[j][3], L2E, b1);
            uint32_t p0 = ex2h2(h2u(__floats2half2_rn(t0, t1)));
            uint32_t p1 = ex2h2(h2u(__floats2half2_rn(t2, t3)));
            P[j][0] = p0; P[j][1] = p1;
            float2 f0 = __half22float2(*reinterpret_cast<__half2*>(&p0));
            float2 f1 = __half22float2(*reinterpret_cast<__half2*>(&p1));
            s0 += f0.x + f0.y;
            s1 += f1.x + f1.y;
        }
        s0 += __shfl_xor_sync(0xffffffffu, s0, 1);
        s0 += __shfl_xor_sync(0xffffffffu, s0, 2);
        s1 += __shfl_xor_sync(0xffffffffu, s1, 1);
        s1 += __shfl_xor_sync(0xffffffffu, s1, 2);
        l0 = l0 * al0 + s0;
        l1 = l1 * al1 + s1;
#pragma unroll
        for (int d = 0; d < 8; d++) {
            O[d][0] *= al0; O[d][1] *= al0;
            O[d][2] *= al1; O[d][3] *= al1;
        }

#pragma unroll
        for (int kj = 0; kj < 4; kj++) {
            uint32_t a0 = P[2 * kj][0];
            uint32_t a1 = P[2 * kj][1];
            uint32_t a2 = P[2 * kj + 1][0];
            uint32_t a3 = P[2 * kj + 1][1];
#pragma unroll
            for (int dp = 0; dp < 4; dp++) {
                uint32_t br[4];
                ldm4t(br, vaddr[dp] + kofs + kj * (16 * VLD * 2));
                mma16(O[2 * dp],     a0, a1, a2, a3, br[0], br[1]);
                mma16(O[2 * dp + 1], a0, a1, a2, a3, br[2], br[3]);
            }
        }
    }

    const float inv0 = 1.0f / l0;
    const float inv1 = 1.0f / l1;
    __half* base = hctx + ((size_t)(bb * SS + qt * 128 + wr0)) * DD + hi * DH;
#pragma unroll
    for (int d = 0; d < 8; d++) {
        *reinterpret_cast<__half2*>(base + (size_t)g * DD + 8 * d + 2 * t4) =
            __floats2half2_rn(O[d][0] * inv0, O[d][1] * inv0);
        *reinterpret_cast<__half2*>(base + (size_t)(g + 8) * DD + 8 * d + 2 * t4) =
            __floats2half2_rn(O[d][2] * inv1, O[d][3] * inv1);
    }
}

// ---------------------------------------------------------------------------
extern "C" void kernel_launch(void* const* d_in, const int* in_sizes, int n_in,
                              void* d_out, int out_size)
{
    const float* query = (const float*)d_in[0];
    const float* key   = (const float*)d_in[1];
    const float* value = (const float*)d_in[2];
    const float* mask  = (const float*)d_in[3];
    const float* Wq    = (const float*)d_in[4];
    const float* bq    = (const float*)d_in[5];
    const float* Wk    = (const float*)d_in[6];
    const float* bk    = (const float*)d_in[7];
    const float* Wv    = (const float*)d_in[8];
    const float* bv    = (const float*)d_in[9];
    const float* Wo    = (const float*)d_in[10];
    const float* bo    = (const float*)d_in[11];
    float* out = (float*)d_out;

    static int configured = 0;
    if (!configured) {
        cudaFuncSetAttribute(proj_qkv_kernel, cudaFuncAttributeMaxDynamicSharedMemorySize, PROJ_SMEM_BYTES);
        cudaFuncSetAttribute(proj_out_kernel, cudaFuncAttributeMaxDynamicSharedMemorySize, PROJ_SMEM_BYTES);
        configured = 1;
    }

    convert_kernel<<<dim3(512, 7), 256>>>(query, key, value, Wq, Wk, Wv, Wo);
    proj_qkv_kernel<<<dim3(8, 32, 3), 256, PROJ_SMEM_BYTES>>>(bq, bk, bv);
    attn_kernel<<<dim3(32, 16), 256>>>(mask);
    proj_out_kernel<<<dim3(8, 32), 256, PROJ_SMEM_BYTES>>>(bo, out);
}

// round 11
// speedup vs baseline: 6.0206x; 1.0039x over previous
#include <cuda_runtime.h>
#include <cuda_fp16.h>
#include <cstdint>

#define BB 2
#define SS 2048
#define DD 1024
#define HH 16
#define DH 64

// ---- scratch (__device__ globals; no allocations allowed) ----
__device__ __half c_q[BB * SS * DD], c_k[BB * SS * DD], c_v[BB * SS * DD];
__device__ __half c_wq[DD * DD], c_wk[DD * DD], c_wv[DD * DD], c_wo[DD * DD];
__device__ __half hq[BB * HH * SS * DH], hk[BB * HH * SS * DH], hv[BB * HH * SS * DH];
__device__ __half hctx[BB * SS * DD];

// ---------------- helpers ----------------
__device__ __forceinline__ uint32_t smem_u32(const void* p) {
    uint32_t a;
    asm("{ .reg .u64 t; cvta.to.shared.u64 t, %1; cvt.u32.u64 %0, t; }" : "=r"(a) : "l"(p));
    return a;
}
__device__ __forceinline__ void cp16(uint32_t d, const void* s) {
    asm volatile("cp.async.cg.shared.global [%0], [%1], 16;" :: "r"(d), "l"(s) : "memory");
}
__device__ __forceinline__ uint32_t h2u(__half2 h) { return *reinterpret_cast<uint32_t*>(&h); }
__device__ __forceinline__ uint32_t ex2h2(uint32_t x) {
    uint32_t r;
    asm("ex2.approx.f16x2 %0, %1;" : "=r"(r) : "r"(x));
    return r;
}
__device__ __forceinline__ void mma16(float* d, uint32_t a0, uint32_t a1, uint32_t a2, uint32_t a3,
                                      uint32_t b0, uint32_t b1) {
    asm volatile(
        "mma.sync.aligned.m16n8k16.row.col.f32.f16.f16.f32 "
        "{%0,%1,%2,%3},{%4,%5,%6,%7},{%8,%9},{%0,%1,%2,%3};"
        : "+f"(d[0]), "+f"(d[1]), "+f"(d[2]), "+f"(d[3])
        : "r"(a0), "r"(a1), "r"(a2), "r"(a3), "r"(b0), "r"(b1));
}
__device__ __forceinline__ void ldm4(uint32_t* r, uint32_t a) {
    asm volatile("ldmatrix.sync.aligned.m8n8.x4.shared.b16 {%0,%1,%2,%3}, [%4];"
        : "=r"(r[0]), "=r"(r[1]), "=r"(r[2]), "=r"(r[3]) : "r"(a));
}
__device__ __forceinline__ void ldm4t(uint32_t* r, uint32_t a) {
    asm volatile("ldmatrix.sync.aligned.m8n8.x4.trans.shared.b16 {%0,%1,%2,%3}, [%4];"
        : "=r"(r[0]), "=r"(r[1]), "=r"(r[2]), "=r"(r[3]) : "r"(a));
}

// ---------------------------------------------------------------------------
// fp32 -> fp16 conversion: 32B reads, 16B stores
// ---------------------------------------------------------------------------
__global__ void __launch_bounds__(256) convert_kernel(
    const float* __restrict__ q, const float* __restrict__ k, const float* __restrict__ v,
    const float* __restrict__ Wq, const float* __restrict__ Wk,
    const float* __restrict__ Wv, const float* __restrict__ Wo)
{
    const float* src; __half* dst; int n;
    switch (blockIdx.y) {
        case 0: src = q;  dst = c_q;  n = BB * SS * DD; break;
        case 1: src = k;  dst = c_k;  n = BB * SS * DD; break;
        case 2: src = v;  dst = c_v;  n = BB * SS * DD; break;
        case 3: src = Wq; dst = c_wq; n = DD * DD; break;
        case 4: src = Wk; dst = c_wk; n = DD * DD; break;
        case 5: src = Wv; dst = c_wv; n = DD * DD; break;
        default: src = Wo; dst = c_wo; n = DD * DD; break;
    }
    const int n8 = n >> 3;
    const float4* s4 = reinterpret_cast<const float4*>(src);
    uint4* d4 = reinterpret_cast<uint4*>(dst);
    for (int i = blockIdx.x * 256 + threadIdx.x; i < n8; i += gridDim.x * 256) {
        float4 f0 = s4[2 * i];
        float4 f1 = s4[2 * i + 1];
        uint4 o;
        o.x = h2u(__floats2half2_rn(f0.x, f0.y));
        o.y = h2u(__floats2half2_rn(f0.z, f0.w));
        o.z = h2u(__floats2half2_rn(f1.x, f1.y));
        o.w = h2u(__floats2half2_rn(f1.z, f1.w));
        d4[i] = o;
    }
}

// ---------------------------------------------------------------------------
// fp16 GEMM, raw mma + ldmatrix: 128x128 CTA tile, BK=32, 256 threads
// (8 warps, 4Mx2N, warp tile 32x64), 4-stage cp.async ring (prefetch 3 ahead,
// wait_group 2), ONE __syncthreads per K-tile, 2 CTAs/SM.
// ---------------------------------------------------------------------------
#define A_PITCH 80      // bytes per A smem row (32 halves + 8 pad)
#define B_PITCH 272     // bytes per B smem row (128 halves + 8 pad)
#define A_STG 10240     // 128 * 80
#define B_STG 8704      // 32 * 272
#define N_STG 4
#define B_BASE (N_STG * A_STG)                     // 40960
#define PROJ_SMEM_BYTES (B_BASE + N_STG * B_STG)   // 75776

__device__ __forceinline__ void gemm_fp16(const __half* __restrict__ A,
                                          const __half* __restrict__ Wm,
                                          const float* __restrict__ bias,
                                          void* __restrict__ outp, int half_head)
{
    extern __shared__ char dsm[];
    const uint32_t sb = smem_u32(dsm);
    const int tid  = threadIdx.x;
    const int warp = tid >> 5;
    const int lane = tid & 31;
    const int g    = lane >> 2;
    const int t4   = lane & 3;
    const int wm   = warp >> 1;    // 0..3 (32-row strip)
    const int wn   = warp & 1;     // 0..1 (64-col strip)
    const int n0   = blockIdx.x * 128;
    const int m0   = blockIdx.y * 128;

    float acc[2][8][4];
#pragma unroll
    for (int mf = 0; mf < 2; mf++)
#pragma unroll
        for (int nf = 0; nf < 8; nf++)
#pragma unroll
            for (int i = 0; i < 4; i++) acc[mf][nf][i] = 0.f;

    // ldmatrix lane base addresses (stage 0)
    const int arow = lane & 15;
    const int acol = (lane >> 4) * 16;   // bytes
    uint32_t aaddr[2];
#pragma unroll
    for (int mf = 0; mf < 2; mf++)
        aaddr[mf] = sb + (wm * 32 + mf * 16 + arow) * A_PITCH + acol;
    const int brow = (lane & 7) + ((lane >> 3) & 1) * 8;
    const int bcol = ((lane >> 4) & 1) * 16;  // bytes
    uint32_t baddr[4];
#pragma unroll
    for (int nfp = 0; nfp < 4; nfp++)
        baddr[nfp] = sb + B_BASE + brow * B_PITCH + (wn * 64 + nfp * 16) * 2 + bcol;

    auto issue = [&](int it) {
        const int kt = it * 32, stg = it % N_STG;
        const uint32_t ad = sb + stg * A_STG;
        const uint32_t bd = sb + B_BASE + stg * B_STG;
#pragma unroll
        for (int t = 0; t < 2; t++) {
            int id = tid + t * 256;                 // A: 128 rows x 4 x 16B
            cp16(ad + (id >> 2) * A_PITCH + (id & 3) * 16,
                 A + (size_t)(m0 + (id >> 2)) * DD + kt + (id & 3) * 8);
        }
#pragma unroll
        for (int t = 0; t < 2; t++) {
            int id = tid + t * 256;                 // B: 32 rows x 16 x 16B
            cp16(bd + (id >> 4) * B_PITCH + (id & 15) * 16,
                 Wm + (size_t)(kt + (id >> 4)) * DD + n0 + (id & 15) * 8);
        }
        asm volatile("cp.async.commit_group;" ::: "memory");
    };

    issue(0);
    issue(1);
    issue(2);
    for (int it = 0; it < 32; it++) {
        if (it < 30)       asm volatile("cp.async.wait_group 2;" ::: "memory");
        else if (it == 30) asm volatile("cp.async.wait_group 1;" ::: "memory");
        else               asm volatile("cp.async.wait_group 0;" ::: "memory");
        __syncthreads();
        if (it + 3 < 32) issue(it + 3);   // writes stage (it-1)%4: fully consumed

        const int stg = it % N_STG;
        const uint32_t aofs = stg * A_STG;
        const uint32_t bofs = stg * B_STG;
#pragma unroll
        for (int kk = 0; kk < 2; kk++) {
            uint32_t aa[2][4];
            ldm4(aa[0], aaddr[0] + aofs + kk * 32);
            ldm4(aa[1], aaddr[1] + aofs + kk * 32);
#pragma unroll
            for (int nfp = 0; nfp < 4; nfp++) {
                uint32_t br[4];
                ldm4t(br, baddr[nfp] + bofs + kk * (16 * B_PITCH));
                mma16(acc[0][2 * nfp],     aa[0][0], aa[0][1], aa[0][2], aa[0][3], br[0], br[1]);
                mma16(acc[0][2 * nfp + 1], aa[0][0], aa[0][1], aa[0][2], aa[0][3], br[2], br[3]);
                mma16(acc[1][2 * nfp],     aa[1][0], aa[1][1], aa[1][2], aa[1][3], br[0], br[1]);
                mma16(acc[1][2 * nfp + 1], aa[1][0], aa[1][1], aa[1][2], aa[1][3], br[2], br[3]);
            }
        }
        // no trailing sync: next iteration's leading sync provides the guarantee
    }

    // Epilogue: bias-add in regs, direct stores
    const int ncb = n0 + wn * 64;
    if (half_head) {
        const int hh = ncb >> 6;
        __half* outh = (__half*)outp;
#pragma unroll
        for (int mf = 0; mf < 2; mf++) {
            const int r0 = m0 + wm * 32 + mf * 16 + g;
            __half* d0 = outh + ((size_t)((r0 >> 11) * HH + hh) * SS + (r0 & 2047)) * DH;
            __half* d1 = outh + ((size_t)(((r0 + 8) >> 11) * HH + hh) * SS + ((r0 + 8) & 2047)) * DH;
#pragma unroll
            for (int nf = 0; nf < 8; nf++) {
                const int c = ncb + nf * 8 + 2 * t4;
                const float bx = bias[c], by = bias[c + 1];
                const int d = nf * 8 + 2 * t4;
                *reinterpret_cast<__half2*>(d0 + d) =
                    __floats2half2_rn(acc[mf][nf][0] + bx, acc[mf][nf][1] + by);
                *reinterpret_cast<__half2*>(d1 + d) =
                    __floats2half2_rn(acc[mf][nf][2] + bx, acc[mf][nf][3] + by);
            }
        }
    } else {
        float* outf = (float*)outp;
#pragma unroll
        for (int mf = 0; mf < 2; mf++) {
            const int r0 = m0 + wm * 32 + mf * 16 + g;
            float* d0 = outf + (size_t)r0 * DD;
            float* d1 = outf + (size_t)(r0 + 8) * DD;
#pragma unroll
            for (int nf = 0; nf < 8; nf++) {
                const int c = ncb + nf * 8 + 2 * t4;
                const float bx = bias[c], by = bias[c + 1];
                *reinterpret_cast<float2*>(d0 + c) =
                    make_float2(acc[mf][nf][0] + bx, acc[mf][nf][1] + by);
                *reinterpret_cast<float2*>(d1 + c) =
                    make_float2(acc[mf][nf][2] + bx, acc[mf][nf][3] + by);
            }
        }
    }
}

__global__ void __launch_bounds__(256, 2) proj_qkv_kernel(
    const float* __restrict__ bq, const float* __restrict__ bk, const float* __restrict__ bv)
{
    const int z = blockIdx.z;
    const __half* A    = (z == 0) ? c_q  : (z == 1) ? c_k  : c_v;
    const __half* W    = (z == 0) ? c_wq : (z == 1) ? c_wk : c_wv;
    const float* bias  = (z == 0) ? bq   : (z == 1) ? bk   : bv;
    __half* out        = (z == 0) ? hq   : (z == 1) ? hk   : hv;
    gemm_fp16(A, W, bias, out, 1);
}

__global__ void __launch_bounds__(256, 2) proj_out_kernel(
    const float* __restrict__ bo, float* __restrict__ out)
{
    gemm_fp16(hctx, c_wo, bo, out, 0);
}

// ---------------------------------------------------------------------------
// Flash attention (unchanged): fp16 mma + ldmatrix, 2-stage cp.async ring,
// softmax via ex2.approx.f16x2.
// ---------------------------------------------------------------------------
#define KLD 72
#define VLD 72
#define KBUF (64 * KLD)
#define KBUF_B (KBUF * 2)

__global__ void __launch_bounds__(256, 2) attn_kernel(const float* __restrict__ mask)
{
    __shared__ __half Ks[2][KBUF];
    __shared__ __half Vs[2][KBUF];
    __shared__ float maskB[2][64];

    const int tid  = threadIdx.x;
    const int warp = tid >> 5;
    const int lane = tid & 31;
    const int g    = lane >> 2;
    const int t4   = lane & 3;
    const int wr0  = warp * 16;
    const int bh   = blockIdx.x;
    const int qt   = blockIdx.y;
    const int bb   = bh >> 4;
    const int hi   = bh & 15;

    const __half* Qg = hq + ((size_t)bh * SS + qt * 128 + wr0) * DH;
    const __half* Kg = hk + (size_t)bh * SS * DH;
    const __half* Vg = hv + (size_t)bh * SS * DH;
    const float*  Mg = mask + (size_t)bb * SS;

    const __half2 qsc = __half2half2(__float2half_rn(0.125f));
    uint32_t Qa[4][4];
#pragma unroll
    for (int kc = 0; kc < 4; kc++) {
        __half2 v0 = *reinterpret_cast<const __half2*>(Qg + (size_t)g * DH + kc * 16 + 2 * t4);
        __half2 v1 = *reinterpret_cast<const __half2*>(Qg + (size_t)(g + 8) * DH + kc * 16 + 2 * t4);
        __half2 v2 = *reinterpret_cast<const __half2*>(Qg + (size_t)g * DH + kc * 16 + 2 * t4 + 8);
        __half2 v3 = *reinterpret_cast<const __half2*>(Qg + (size_t)(g + 8) * DH + kc * 16 + 2 * t4 + 8);
        Qa[kc][0] = h2u(__hmul2(v0, qsc));
        Qa[kc][1] = h2u(__hmul2(v1, qsc));
        Qa[kc][2] = h2u(__hmul2(v2, qsc));
        Qa[kc][3] = h2u(__hmul2(v3, qsc));
    }

    const int krow = (lane & 7) + ((lane >> 4) & 1) * 8;
    const int kcol = ((lane >> 3) & 1) * 8;
    uint32_t kaddr[4];
#pragma unroll
    for (int jp = 0; jp < 4; jp++)
        kaddr[jp] = smem_u32(&Ks[0][(16 * jp + krow) * KLD + kcol]);
    const int vrow = (lane & 7) + ((lane >> 3) & 1) * 8;
    const int vcol = ((lane >> 4) & 1) * 8;
    uint32_t vaddr[4];
#pragma unroll
    for (int dp = 0; dp < 4; dp++)
        vaddr[dp] = smem_u32(&Vs[0][vrow * VLD + 16 * dp + vcol]);

    auto prefetch = [&](int ti) {
        const int kt0 = ti * 64, buf = ti & 1;
#pragma unroll
        for (int t = 0; t < 2; t++) {
            int idx = tid + t * 256;
            int r = idx >> 3, c = (idx & 7) * 8;
            cp16(smem_u32(&Ks[buf][r * KLD + c]), Kg + (size_t)(kt0 + r) * DH + c);
            cp16(smem_u32(&Vs[buf][r * VLD + c]), Vg + (size_t)(kt0 + r) * DH + c);
        }
        if (tid < 16) cp16(smem_u32(&maskB[buf][tid * 4]), Mg + kt0 + tid * 4);
        asm volatile("cp.async.commit_group;" ::: "memory");
    };

    float O[8][4];
#pragma unroll
    for (int d = 0; d < 8; d++) { O[d][0] = O[d][1] = O[d][2] = O[d][3] = 0.f; }
    float m0 = -1e30f, m1 = -1e30f, l0 = 0.f, l1 = 0.f;
    const float L2E = 1.44269504f;

    prefetch(0);
    for (int ti = 0; ti < 32; ti++) {
        asm volatile("cp.async.wait_group 0;" ::: "memory");
        __syncthreads();
        if (ti + 1 < 32) prefetch(ti + 1);

        const int buf = ti & 1;
        const uint32_t kofs = buf * KBUF_B;

        float S[8][4];
#pragma unroll
        for (int j = 0; j < 8; j++) { S[j][0] = S[j][1] = S[j][2] = S[j][3] = 0.f; }
#pragma unroll
        for (int kc = 0; kc < 4; kc++) {
#pragma unroll
            for (int jp = 0; jp < 4; jp++) {
                uint32_t br[4];
                ldm4(br, kaddr[jp] + kofs + kc * 32);
                mma16(S[2 * jp],     Qa[kc][0], Qa[kc][1], Qa[kc][2], Qa[kc][3], br[0], br[1]);
                mma16(S[2 * jp + 1], Qa[kc][0], Qa[kc][1], Qa[kc][2], Qa[kc][3], br[2], br[3]);
            }
        }

        float mx0 = -1e30f, mx1 = -1e30f;
#pragma unroll
        for (int j = 0; j < 8; j++) {
            float k0 = maskB[buf][8 * j + 2 * t4]     * -1e9f;
            float k1 = maskB[buf][8 * j + 2 * t4 + 1] * -1e9f;
            S[j][0] += k0; S[j][1] += k1; S[j][2] += k0; S[j][3] += k1;
            mx0 = fmaxf(mx0, fmaxf(S[j][0], S[j][1]));
            mx1 = fmaxf(mx1, fmaxf(S[j][2], S[j][3]));
        }
        mx0 = fmaxf(mx0, __shfl_xor_sync(0xffffffffu, mx0, 1));
        mx0 = fmaxf(mx0, __shfl_xor_sync(0xffffffffu, mx0, 2));
        mx1 = fmaxf(mx1, __shfl_xor_sync(0xffffffffu, mx1, 1));
        mx1 = fmaxf(mx1, __shfl_xor_sync(0xffffffffu, mx1, 2));
        const float nm0 = fmaxf(m0, mx0);
        const float nm1 = fmaxf(m1, mx1);
        const float al0 = __expf(m0 - nm0);
        const float al1 = __expf(m1 - nm1);
        m0 = nm0; m1 = nm1;

        uint32_t P[8][2];
        const float b0 = -nm0 * L2E, b1 = -nm1 * L2E;
        float s0 = 0.f, s1 = 0.f;
#pragma unroll
        for (int j = 0; j < 8; j++) {
            float t0 = fmaf(S[j][0], L2E, b0);
            float t1 = fmaf(S[j][1], L2E, b0);
            float t2 = fmaf(S[j][2], L2E, b1);
            float t3 = fmaf(S[j][3], L2E, b1);
            uint32_t p0 = ex2h2(h2u(__floats2half2_rn(t0, t1)));
            uint32_t p1 = ex2h2(h2u(__floats2half2_rn(t2, t3)));
            P[j][0] = p0; P[j][1] = p1;
            float2 f0 = __half22float2(*reinterpret_cast<__half2*>(&p0));
            float2 f1 = __half22float2(*reinterpret_cast<__half2*>(&p1));
            s0 += f0.x + f0.y;
            s1 += f1.x + f1.y;
        }
        s0 += __shfl_xor_sync(0xffffffffu, s0, 1);
        s0 += __shfl_xor_sync(0xffffffffu, s0, 2);
        s1 += __shfl_xor_sync(0xffffffffu, s1, 1);
        s1 += __shfl_xor_sync(0xffffffffu, s1, 2);
        l0 = l0 * al0 + s0;
        l1 = l1 * al1 + s1;
#pragma unroll
        for (int d = 0; d < 8; d++) {
            O[d][0] *= al0; O[d][1] *= al0;
            O[d][2] *= al1; O[d][3] *= al1;
        }

#pragma unroll
        for (int kj = 0; kj < 4; kj++) {
            uint32_t a0 = P[2 * kj][0];
            uint32_t a1 = P[2 * kj][1];
            uint32_t a2 = P[2 * kj + 1][0];
            uint32_t a3 = P[2 * kj + 1][1];
#pragma unroll
            for (int dp = 0; dp < 4; dp++) {
                uint32_t br[4];
                ldm4t(br, vaddr[dp] + kofs + kj * (16 * VLD * 2));
                mma16(O[2 * dp],     a0, a1, a2, a3, br[0], br[1]);
                mma16(O[2 * dp + 1], a0, a1, a2, a3, br[2], br[3]);
            }
        }
    }

    const float inv0 = 1.0f / l0;
    const float inv1 = 1.0f / l1;
    __half* base = hctx + ((size_t)(bb * SS + qt * 128 + wr0)) * DD + hi * DH;
#pragma unroll
    for (int d = 0; d < 8; d++) {
        *reinterpret_cast<__half2*>(base + (size_t)g * DD + 8 * d + 2 * t4) =
            __floats2half2_rn(O[d][0] * inv0, O[d][1] * inv0);
        *reinterpret_cast<__half2*>(base + (size_t)(g + 8) * DD + 8 * d + 2 * t4) =
            __floats2half2_rn(O[d][2] * inv1, O[d][3] * inv1);
    }
}

// ---------------------------------------------------------------------------
extern "C" void kernel_launch(void* const* d_in, const int* in_sizes, int n_in,
                              void* d_out, int out_size)
{
    const float* query = (const float*)d_in[0];
    const float* key   = (const float*)d_in[1];
    const float* value = (const float*)d_in[2];
    const float* mask  = (const float*)d_in[3];
    const float* Wq    = (const float*)d_in[4];
    const float* bq    = (const float*)d_in[5];
    const float* Wk    = (const float*)d_in[6];
    const float* bk    = (const float*)d_in[7];
    const float* Wv    = (const float*)d_in[8];
    const float* bv    = (const float*)d_in[9];
    const float* Wo    = (const float*)d_in[10];
    const float* bo    = (const float*)d_in[11];
    float* out = (float*)d_out;

    static int configured = 0;
    if (!configured) {
        cudaFuncSetAttribute(proj_qkv_kernel, cudaFuncAttributeMaxDynamicSharedMemorySize, PROJ_SMEM_BYTES);
        cudaFuncSetAttribute(proj_out_kernel, cudaFuncAttributeMaxDynamicSharedMemorySize, PROJ_SMEM_BYTES);
        configured = 1;
    }

    convert_kernel<<<dim3(512, 7), 256>>>(query, key, value, Wq, Wk, Wv, Wo);
    proj_qkv_kernel<<<dim3(8, 32, 3), 256, PROJ_SMEM_BYTES>>>(bq, bk, bv);
    attn_kernel<<<dim3(32, 16), 256>>>(mask);
    proj_out_kernel<<<dim3(8, 32), 256, PROJ_SMEM_BYTES>>>(bo, out);
}

// round 13
// speedup vs baseline: 6.4814x; 1.0765x over previous
#include <cuda_runtime.h>
#include <cuda_fp16.h>
#include <cstdint>

#define BB 2
#define SS 2048
#define DD 1024
#define HH 16
#define DH 64

// ---- scratch (__device__ globals; no allocations allowed) ----
__device__ __half c_q[BB * SS * DD], c_k[BB * SS * DD], c_v[BB * SS * DD];
__device__ __half c_wq[DD * DD], c_wk[DD * DD], c_wv[DD * DD], c_wo[DD * DD];
__device__ __half hq[BB * HH * SS * DH], hk[BB * HH * SS * DH], hv[BB * HH * SS * DH];
__device__ __half hctx[BB * SS * DD];

// ---------------- helpers ----------------
__device__ __forceinline__ uint32_t smem_u32(const void* p) {
    uint32_t a;
    asm("{ .reg .u64 t; cvta.to.shared.u64 t, %1; cvt.u32.u64 %0, t; }" : "=r"(a) : "l"(p));
    return a;
}
__device__ __forceinline__ void cp16(uint32_t d, const void* s) {
    asm volatile("cp.async.cg.shared.global [%0], [%1], 16;" :: "r"(d), "l"(s) : "memory");
}
__device__ __forceinline__ uint32_t h2u(__half2 h) { return *reinterpret_cast<uint32_t*>(&h); }
__device__ __forceinline__ uint32_t ex2h2(uint32_t x) {
    uint32_t r;
    asm("ex2.approx.f16x2 %0, %1;" : "=r"(r) : "r"(x));
    return r;
}
__device__ __forceinline__ void mma16(float* d, uint32_t a0, uint32_t a1, uint32_t a2, uint32_t a3,
                                      uint32_t b0, uint32_t b1) {
    asm volatile(
        "mma.sync.aligned.m16n8k16.row.col.f32.f16.f16.f32 "
        "{%0,%1,%2,%3},{%4,%5,%6,%7},{%8,%9},{%0,%1,%2,%3};"
        : "+f"(d[0]), "+f"(d[1]), "+f"(d[2]), "+f"(d[3])
        : "r"(a0), "r"(a1), "r"(a2), "r"(a3), "r"(b0), "r"(b1));
}
__device__ __forceinline__ void ldm4(uint32_t* r, uint32_t a) {
    asm volatile("ldmatrix.sync.aligned.m8n8.x4.shared.b16 {%0,%1,%2,%3}, [%4];"
        : "=r"(r[0]), "=r"(r[1]), "=r"(r[2]), "=r"(r[3]) : "r"(a));
}
__device__ __forceinline__ void ldm4t(uint32_t* r, uint32_t a) {
    asm volatile("ldmatrix.sync.aligned.m8n8.x4.trans.shared.b16 {%0,%1,%2,%3}, [%4];"
        : "=r"(r[0]), "=r"(r[1]), "=r"(r[2]), "=r"(r[3]) : "r"(a));
}

// ---------------------------------------------------------------------------
// fp32 -> fp16 conversion: 32B reads, 16B stores
// ---------------------------------------------------------------------------
__global__ void __launch_bounds__(256) convert_kernel(
    const float* __restrict__ q, const float* __restrict__ k, const float* __restrict__ v,
    const float* __restrict__ Wq, const float* __restrict__ Wk,
    const float* __restrict__ Wv, const float* __restrict__ Wo)
{
    const float* src; __half* dst; int n;
    switch (blockIdx.y) {
        case 0: src = q;  dst = c_q;  n = BB * SS * DD; break;
        case 1: src = k;  dst = c_k;  n = BB * SS * DD; break;
        case 2: src = v;  dst = c_v;  n = BB * SS * DD; break;
        case 3: src = Wq; dst = c_wq; n = DD * DD; break;
        case 4: src = Wk; dst = c_wk; n = DD * DD; break;
        case 5: src = Wv; dst = c_wv; n = DD * DD; break;
        default: src = Wo; dst = c_wo; n = DD * DD; break;
    }
    const int n8 = n >> 3;
    const float4* s4 = reinterpret_cast<const float4*>(src);
    uint4* d4 = reinterpret_cast<uint4*>(dst);
    for (int i = blockIdx.x * 256 + threadIdx.x; i < n8; i += gridDim.x * 256) {
        float4 f0 = s4[2 * i];
        float4 f1 = s4[2 * i + 1];
        uint4 o;
        o.x = h2u(__floats2half2_rn(f0.x, f0.y));
        o.y = h2u(__floats2half2_rn(f0.z, f0.w));
        o.z = h2u(__floats2half2_rn(f1.x, f1.y));
        o.w = h2u(__floats2half2_rn(f1.z, f1.w));
        d4[i] = o;
    }
}

// ---------------------------------------------------------------------------
// fp16 GEMM, raw mma + ldmatrix: 128x128 CTA tile, BK=32, 128 threads
// (4 warps, 2Mx2N, warp tile 64x64 -> B fragments re-read x2 instead of x4),
// 4-stage cp.async ring, one __syncthreads per K-tile, 2 CTAs/SM.
// A tile: 128 rows x 4 chunks(16B) = 512 chunks. B tile: 32 rows x 16 = 512.
// ---------------------------------------------------------------------------
#define A_PITCH 80      // bytes per A smem row (32 halves + 8 pad)
#define B_PITCH 272     // bytes per B smem row (128 halves + 8 pad)
#define A_STG 10240     // 128 * 80
#define B_STG 8704      // 32 * 272
#define N_STG 4
#define B_BASE (N_STG * A_STG)                     // 40960
#define PROJ_SMEM_BYTES (B_BASE + N_STG * B_STG)   // 75776

__device__ __forceinline__ void gemm_fp16(const __half* __restrict__ A,
                                          const __half* __restrict__ Wm,
                                          const float* __restrict__ bias,
                                          void* __restrict__ outp, int half_head)
{
    extern __shared__ char dsm[];
    const uint32_t sb = smem_u32(dsm);
    const int tid  = threadIdx.x;
    const int warp = tid >> 5;
    const int lane = tid & 31;
    const int g    = lane >> 2;
    const int t4   = lane & 3;
    const int wm   = warp >> 1;    // 0..1 (64-row strip)
    const int wn   = warp & 1;     // 0..1 (64-col strip)
    const int n0   = blockIdx.x * 128;
    const int m0   = blockIdx.y * 128;

    float acc[4][8][4];
#pragma unroll
    for (int mf = 0; mf < 4; mf++)
#pragma unroll
        for (int nf = 0; nf < 8; nf++)
#pragma unroll
            for (int i = 0; i < 4; i++) acc[mf][nf][i] = 0.f;

    // ldmatrix lane base addresses (stage 0)
    const int arow = lane & 15;
    const int acol = (lane >> 4) * 16;   // bytes
    const uint32_t aaddr0 = sb + (wm * 64 + arow) * A_PITCH + acol;
    const int brow = (lane & 7) + ((lane >> 3) & 1) * 8;
    const int bcol = ((lane >> 4) & 1) * 16;  // bytes
    uint32_t baddr[4];
#pragma unroll
    for (int nfp = 0; nfp < 4; nfp++)
        baddr[nfp] = sb + B_BASE + brow * B_PITCH + (wn * 64 + nfp * 16) * 2 + bcol;

    auto issue = [&](int it) {
        const int kt = it * 32, stg = it % N_STG;
        const uint32_t ad = sb + stg * A_STG;
        const uint32_t bd = sb + B_BASE + stg * B_STG;
#pragma unroll
        for (int t = 0; t < 4; t++) {
            int id = tid + t * 128;                 // A: 512 chunks of 16B
            cp16(ad + (id >> 2) * A_PITCH + (id & 3) * 16,
                 A + (size_t)(m0 + (id >> 2)) * DD + kt + (id & 3) * 8);
        }
#pragma unroll
        for (int t = 0; t < 4; t++) {
            int id = tid + t * 128;                 // B: 512 chunks of 16B
            cp16(bd + (id >> 4) * B_PITCH + (id & 15) * 16,
                 Wm + (size_t)(kt + (id >> 4)) * DD + n0 + (id & 15) * 8);
        }
        asm volatile("cp.async.commit_group;" ::: "memory");
    };

    issue(0);
    issue(1);
    issue(2);
    for (int it = 0; it < 32; it++) {
        if (it < 30)       asm volatile("cp.async.wait_group 2;" ::: "memory");
        else if (it == 30) asm volatile("cp.async.wait_group 1;" ::: "memory");
        else               asm volatile("cp.async.wait_group 0;" ::: "memory");
        __syncthreads();
        if (it + 3 < 32) issue(it + 3);

        const int stg = it % N_STG;
        const uint32_t aofs = stg * A_STG;
        const uint32_t bofs = stg * B_STG;
#pragma unroll
        for (int kk = 0; kk < 2; kk++) {
            uint32_t aa[4][4];
#pragma unroll
            for (int mf = 0; mf < 4; mf++)
                ldm4(aa[mf], aaddr0 + mf * (16 * A_PITCH) + aofs + kk * 32);
#pragma unroll
            for (int nfp = 0; nfp < 4; nfp++) {
                uint32_t br[4];
                ldm4t(br, baddr[nfp] + bofs + kk * (16 * B_PITCH));
#pragma unroll
                for (int mf = 0; mf < 4; mf++) {
                    mma16(acc[mf][2 * nfp],     aa[mf][0], aa[mf][1], aa[mf][2], aa[mf][3], br[0], br[1]);
                    mma16(acc[mf][2 * nfp + 1], aa[mf][0], aa[mf][1], aa[mf][2], aa[mf][3], br[2], br[3]);
                }
            }
        }
    }

    // Epilogue: bias-add in regs, direct stores
    const int ncb = n0 + wn * 64;
    if (half_head) {
        const int hh = ncb >> 6;
        __half* outh = (__half*)outp;
#pragma unroll
        for (int mf = 0; mf < 4; mf++) {
            const int r0 = m0 + wm * 64 + mf * 16 + g;
            __half* d0 = outh + ((size_t)((r0 >> 11) * HH + hh) * SS + (r0 & 2047)) * DH;
            __half* d1 = outh + ((size_t)(((r0 + 8) >> 11) * HH + hh) * SS + ((r0 + 8) & 2047)) * DH;
#pragma unroll
            for (int nf = 0; nf < 8; nf++) {
                const int c = ncb + nf * 8 + 2 * t4;
                const float bx = bias[c], by = bias[c + 1];
                const int d = nf * 8 + 2 * t4;
                *reinterpret_cast<__half2*>(d0 + d) =
                    __floats2half2_rn(acc[mf][nf][0] + bx, acc[mf][nf][1] + by);
                *reinterpret_cast<__half2*>(d1 + d) =
                    __floats2half2_rn(acc[mf][nf][2] + bx, acc[mf][nf][3] + by);
            }
        }
    } else {
        float* outf = (float*)outp;
#pragma unroll
        for (int mf = 0; mf < 4; mf++) {
            const int r0 = m0 + wm * 64 + mf * 16 + g;
            float* d0 = outf + (size_t)r0 * DD;
            float* d1 = outf + (size_t)(r0 + 8) * DD;
#pragma unroll
            for (int nf = 0; nf < 8; nf++) {
                const int c = ncb + nf * 8 + 2 * t4;
                const float bx = bias[c], by = bias[c + 1];
                *reinterpret_cast<float2*>(d0 + c) =
                    make_float2(acc[mf][nf][0] + bx, acc[mf][nf][1] + by);
                *reinterpret_cast<float2*>(d1 + c) =
                    make_float2(acc[mf][nf][2] + bx, acc[mf][nf][3] + by);
            }
        }
    }
}

__global__ void __launch_bounds__(128, 2) proj_qkv_kernel(
    const float* __restrict__ bq, const float* __restrict__ bk, const float* __restrict__ bv)
{
    const int z = blockIdx.z;
    const __half* A    = (z == 0) ? c_q  : (z == 1) ? c_k  : c_v;
    const __half* W    = (z == 0) ? c_wq : (z == 1) ? c_wk : c_wv;
    const float* bias  = (z == 0) ? bq   : (z == 1) ? bk   : bv;
    __half* out        = (z == 0) ? hq   : (z == 1) ? hk   : hv;
    gemm_fp16(A, W, bias, out, 1);
}

__global__ void __launch_bounds__(128, 2) proj_out_kernel(
    const float* __restrict__ bo, float* __restrict__ out)
{
    gemm_fp16(hctx, c_wo, bo, out, 0);
}

// ---------------------------------------------------------------------------
// Flash attention (unchanged): fp16 mma + ldmatrix, 2-stage cp.async ring,
// softmax via ex2.approx.f16x2.
// ---------------------------------------------------------------------------
#define KLD 72
#define VLD 72
#define KBUF (64 * KLD)
#define KBUF_B (KBUF * 2)

__global__ void __launch_bounds__(256, 2) attn_kernel(const float* __restrict__ mask)
{
    __shared__ __half Ks[2][KBUF];
    __shared__ __half Vs[2][KBUF];
    __shared__ float maskB[2][64];

    const int tid  = threadIdx.x;
    const int warp = tid >> 5;
    const int lane = tid & 31;
    const int g    = lane >> 2;
    const int t4   = lane & 3;
    const int wr0  = warp * 16;
    const int bh   = blockIdx.x;
    const int qt   = blockIdx.y;
    const int bb   = bh >> 4;
    const int hi   = bh & 15;

    const __half* Qg = hq + ((size_t)bh * SS + qt * 128 + wr0) * DH;
    const __half* Kg = hk + (size_t)bh * SS * DH;
    const __half* Vg = hv + (size_t)bh * SS * DH;
    const float*  Mg = mask + (size_t)bb * SS;

    const __half2 qsc = __half2half2(__float2half_rn(0.125f));
    uint32_t Qa[4][4];
#pragma unroll
    for (int kc = 0; kc < 4; kc++) {
        __half2 v0 = *reinterpret_cast<const __half2*>(Qg + (size_t)g * DH + kc * 16 + 2 * t4);
        __half2 v1 = *reinterpret_cast<const __half2*>(Qg + (size_t)(g + 8) * DH + kc * 16 + 2 * t4);
        __half2 v2 = *reinterpret_cast<const __half2*>(Qg + (size_t)g * DH + kc * 16 + 2 * t4 + 8);
        __half2 v3 = *reinterpret_cast<const __half2*>(Qg + (size_t)(g + 8) * DH + kc * 16 + 2 * t4 + 8);
        Qa[kc][0] = h2u(__hmul2(v0, qsc));
        Qa[kc][1] = h2u(__hmul2(v1, qsc));
        Qa[kc][2] = h2u(__hmul2(v2, qsc));
        Qa[kc][3] = h2u(__hmul2(v3, qsc));
    }

    const int krow = (lane & 7) + ((lane >> 4) & 1) * 8;
    const int kcol = ((lane >> 3) & 1) * 8;
    uint32_t kaddr[4];
#pragma unroll
    for (int jp = 0; jp < 4; jp++)
        kaddr[jp] = smem_u32(&Ks[0][(16 * jp + krow) * KLD + kcol]);
    const int vrow = (lane & 7) + ((lane >> 3) & 1) * 8;
    const int vcol = ((lane >> 4) & 1) * 8;
    uint32_t vaddr[4];
#pragma unroll
    for (int dp = 0; dp < 4; dp++)
        vaddr[dp] = smem_u32(&Vs[0][vrow * VLD + 16 * dp + vcol]);

    auto prefetch = [&](int ti) {
        const int kt0 = ti * 64, buf = ti & 1;
#pragma unroll
        for (int t = 0; t < 2; t++) {
            int idx = tid + t * 256;
            int r = idx >> 3, c = (idx & 7) * 8;
            cp16(smem_u32(&Ks[buf][r * KLD + c]), Kg + (size_t)(kt0 + r) * DH + c);
            cp16(smem_u32(&Vs[buf][r * VLD + c]), Vg + (size_t)(kt0 + r) * DH + c);
        }
        if (tid < 16) cp16(smem_u32(&maskB[buf][tid * 4]), Mg + kt0 + tid * 4);
        asm volatile("cp.async.commit_group;" ::: "memory");
    };

    float O[8][4];
#pragma unroll
    for (int d = 0; d < 8; d++) { O[d][0] = O[d][1] = O[d][2] = O[d][3] = 0.f; }
    float m0 = -1e30f, m1 = -1e30f, l0 = 0.f, l1 = 0.f;
    const float L2E = 1.44269504f;

    prefetch(0);
    for (int ti = 0; ti < 32; ti++) {
        asm volatile("cp.async.wait_group 0;" ::: "memory");
        __syncthreads();
        if (ti + 1 < 32) prefetch(ti + 1);

        const int buf = ti & 1;
        const uint32_t kofs = buf * KBUF_B;

        float S[8][4];
#pragma unroll
        for (int j = 0; j < 8; j++) { S[j][0] = S[j][1] = S[j][2] = S[j][3] = 0.f; }
#pragma unroll
        for (int kc = 0; kc < 4; kc++) {
#pragma unroll
            for (int jp = 0; jp < 4; jp++) {
                uint32_t br[4];
                ldm4(br, kaddr[jp] + kofs + kc * 32);
                mma16(S[2 * jp],     Qa[kc][0], Qa[kc][1], Qa[kc][2], Qa[kc][3], br[0], br[1]);
                mma16(S[2 * jp + 1], Qa[kc][0], Qa[kc][1], Qa[kc][2], Qa[kc][3], br[2], br[3]);
            }
        }

        float mx0 = -1e30f, mx1 = -1e30f;
#pragma unroll
        for (int j = 0; j < 8; j++) {
            float k0 = maskB[buf][8 * j + 2 * t4]     * -1e9f;
            float k1 = maskB[buf][8 * j + 2 * t4 + 1] * -1e9f;
            S[j][0] += k0; S[j][1] += k1; S[j][2] += k0; S[j][3] += k1;
            mx0 = fmaxf(mx0, fmaxf(S[j][0], S[j][1]));
            mx1 = fmaxf(mx1, fmaxf(S[j][2], S[j][3]));
        }
        mx0 = fmaxf(mx0, __shfl_xor_sync(0xffffffffu, mx0, 1));
        mx0 = fmaxf(mx0, __shfl_xor_sync(0xffffffffu, mx0, 2));
        mx1 = fmaxf(mx1, __shfl_xor_sync(0xffffffffu, mx1, 1));
        mx1 = fmaxf(mx1, __shfl_xor_sync(0xffffffffu, mx1, 2));
        const float nm0 = fmaxf(m0, mx0);
        const float nm1 = fmaxf(m1, mx1);
        const float al0 = __expf(m0 - nm0);
        const float al1 = __expf(m1 - nm1);
        m0 = nm0; m1 = nm1;

        uint32_t P[8][2];
        const float b0 = -nm0 * L2E, b1 = -nm1 * L2E;
        float s0 = 0.f, s1 = 0.f;
#pragma unroll
        for (int j = 0; j < 8; j++) {
            float t0 = fmaf(S[j][0], L2E, b0);
            float t1 = fmaf(S[j][1], L2E, b0);
            float t2 = fmaf(S[j][2], L2E, b1);
            float t3 = fmaf(S[j][3], L2E, b1);
            uint32_t p0 = ex2h2(h2u(__floats2half2_rn(t0, t1)));
            uint32_t p1 = ex2h2(h2u(__floats2half2_rn(t2, t3)));
            P[j][0] = p0; P[j][1] = p1;
            float2 f0 = __half22float2(*reinterpret_cast<__half2*>(&p0));
            float2 f1 = __half22float2(*reinterpret_cast<__half2*>(&p1));
            s0 += f0.x + f0.y;
            s1 += f1.x + f1.y;
        }
        s0 += __shfl_xor_sync(0xffffffffu, s0, 1);
        s0 += __shfl_xor_sync(0xffffffffu, s0, 2);
        s1 += __shfl_xor_sync(0xffffffffu, s1, 1);
        s1 += __shfl_xor_sync(0xffffffffu, s1, 2);
        l0 = l0 * al0 + s0;
        l1 = l1 * al1 + s1;
#pragma unroll
        for (int d = 0; d < 8; d++) {
            O[d][0] *= al0; O[d][1] *= al0;
            O[d][2] *= al1; O[d][3] *= al1;
        }

#pragma unroll
        for (int kj = 0; kj < 4; kj++) {
            uint32_t a0 = P[2 * kj][0];
            uint32_t a1 = P[2 * kj][1];
            uint32_t a2 = P[2 * kj + 1][0];
            uint32_t a3 = P[2 * kj + 1][1];
#pragma unroll
            for (int dp = 0; dp < 4; dp++) {
                uint32_t br[4];
                ldm4t(br, vaddr[dp] + kofs + kj * (16 * VLD * 2));
                mma16(O[2 * dp],     a0, a1, a2, a3, br[0], br[1]);
                mma16(O[2 * dp + 1], a0, a1, a2, a3, br[2], br[3]);
            }
        }
    }

    const float inv0 = 1.0f / l0;
    const float inv1 = 1.0f / l1;
    __half* base = hctx + ((size_t)(bb * SS + qt * 128 + wr0)) * DD + hi * DH;
#pragma unroll
    for (int d = 0; d < 8; d++) {
        *reinterpret_cast<__half2*>(base + (size_t)g * DD + 8 * d + 2 * t4) =
            __floats2half2_rn(O[d][0] * inv0, O[d][1] * inv0);
        *reinterpret_cast<__half2*>(base + (size_t)(g + 8) * DD + 8 * d + 2 * t4) =
            __floats2half2_rn(O[d][2] * inv1, O[d][3] * inv1);
    }
}

// ---------------------------------------------------------------------------
extern "C" void kernel_launch(void* const* d_in, const int* in_sizes, int n_in,
                              void* d_out, int out_size)
{
    const float* query = (const float*)d_in[0];
    const float* key   = (const float*)d_in[1];
    const float* value = (const float*)d_in[2];
    const float* mask  = (const float*)d_in[3];
    const float* Wq    = (const float*)d_in[4];
    const float* bq    = (const float*)d_in[5];
    const float* Wk    = (const float*)d_in[6];
    const float* bk    = (const float*)d_in[7];
    const float* Wv    = (const float*)d_in[8];
    const float* bv    = (const float*)d_in[9];
    const float* Wo    = (const float*)d_in[10];
    const float* bo    = (const float*)d_in[11];
    float* out = (float*)d_out;

    static int configured = 0;
    if (!configured) {
        cudaFuncSetAttribute(proj_qkv_kernel, cudaFuncAttributeMaxDynamicSharedMemorySize, PROJ_SMEM_BYTES);
        cudaFuncSetAttribute(proj_out_kernel, cudaFuncAttributeMaxDynamicSharedMemorySize, PROJ_SMEM_BYTES);
        configured = 1;
    }

    convert_kernel<<<dim3(512, 7), 256>>>(query, key, value, Wq, Wk, Wv, Wo);
    proj_qkv_kernel<<<dim3(8, 32, 3), 128, PROJ_SMEM_BYTES>>>(bq, bk, bv);
    attn_kernel<<<dim3(32, 16), 256>>>(mask);
    proj_out_kernel<<<dim3(8, 32), 128, PROJ_SMEM_BYTES>>>(bo, out);
}